// round 11
// baseline (speedup 1.0000x reference)
#include <cuda_runtime.h>
#include <cuda_bf16.h>
#include <cstdint>
#include <cstddef>

#define K_CB   2048
#define D_DIM  512
#define B_DIM  16
#define N_DIM  8192
#define M_ROWS (B_DIM * N_DIM)
#define MARGIN 8.0f

// -------- device scratch: int8 quantized planes (packed 4 dims/word) --------
__device__ uint32_t g_Aq[(size_t)M_ROWS * 128];   // 64 MB
__device__ uint32_t g_Bq[(size_t)K_CB * 128];     // 1 MB
__device__ float    g_sxr[M_ROWS];                // 2*sx per row folded at use
__device__ float    g_se[K_CB];
__device__ float    g_e2[K_CB];
__device__ int      g_ind[M_ROWS];
__device__ int      g_lightm[M_ROWS];
__device__ int      g_cand[(size_t)M_ROWS * 4];
__device__ int      g_fullm[M_ROWS];
__device__ int      g_nlight;
__device__ int      g_nfull;

// -------- helpers --------
__device__ __forceinline__ uint32_t smem_u32(const void* p) {
    uint32_t a;
    asm("{ .reg .u64 t; cvta.to.shared.u64 t, %1; cvt.u32.u64 %0, t; }" : "=r"(a) : "l"(p));
    return a;
}
#define CP_A16(s, g) \
    asm volatile("cp.async.cg.shared.global [%0], [%1], 16;" :: "r"(s), "l"(g) : "memory")
#define CP_COMMIT() asm volatile("cp.async.commit_group;" ::: "memory")
#define CP_WAIT(n)  asm volatile("cp.async.wait_group %0;" :: "n"(n) : "memory")

__device__ __forceinline__ void ldsm4(uint32_t* r, uint32_t addr) {
    asm volatile("ldmatrix.sync.aligned.m8n8.x4.shared.b16 {%0,%1,%2,%3}, [%4];"
                 : "=r"(r[0]), "=r"(r[1]), "=r"(r[2]), "=r"(r[3]) : "r"(addr));
}
__device__ __forceinline__ void mma16832(int* c, const uint32_t* a, const uint32_t* b) {
    asm volatile("mma.sync.aligned.m16n8k32.row.col.s32.s8.s8.s32 "
                 "{%0,%1,%2,%3}, {%4,%5,%6,%7}, {%8,%9}, {%0,%1,%2,%3};"
                 : "+r"(c[0]), "+r"(c[1]), "+r"(c[2]), "+r"(c[3])
                 : "r"(a[0]), "r"(a[1]), "r"(a[2]), "r"(a[3]), "r"(b[0]), "r"(b[1]));
}
__device__ __forceinline__ int q8(float v, float rinv) {
    int q = __float2int_rn(v * rinv);
    return max(-127, min(127, q));
}

// -------- prep: codebook quantize + e2 --------
__global__ __launch_bounds__(128) void prep_embed_kernel(const float* __restrict__ embed) {
    __shared__ float er[512];
    __shared__ float wmx[4], wsm[4];
    int k = blockIdx.x;
    const float* row = embed + (size_t)k * D_DIM;
    int tid = threadIdx.x;
    float4 v = ((const float4*)row)[tid];
    ((float4*)er)[tid] = v;
    float mx = fmaxf(fmaxf(fabsf(v.x), fabsf(v.y)), fmaxf(fabsf(v.z), fabsf(v.w)));
    float s2 = v.x * v.x + v.y * v.y + v.z * v.z + v.w * v.w;
    #pragma unroll
    for (int o = 16; o > 0; o >>= 1) {
        mx = fmaxf(mx, __shfl_xor_sync(0xffffffffu, mx, o));
        s2 += __shfl_xor_sync(0xffffffffu, s2, o);
    }
    if ((tid & 31) == 0) { wmx[tid >> 5] = mx; wsm[tid >> 5] = s2; }
    __syncthreads();
    mx = fmaxf(fmaxf(wmx[0], wmx[1]), fmaxf(wmx[2], wmx[3]));
    float e2 = wsm[0] + wsm[1] + wsm[2] + wsm[3];
    float s = fmaxf(mx, 1e-20f) * (1.0f / 127.0f);
    float rinv = 1.0f / s;
    if (tid == 0) { g_se[k] = s; g_e2[k] = e2; }
    const float* p = er + tid * 4;
    uint32_t w = (uint32_t)(q8(p[0], rinv) & 0xff)
               | ((uint32_t)(q8(p[1], rinv) & 0xff) << 8)
               | ((uint32_t)(q8(p[2], rinv) & 0xff) << 16)
               | ((uint32_t)(q8(p[3], rinv) & 0xff) << 24);
    g_Bq[(size_t)k * 128 + tid] = w;
    if (blockIdx.x == 0 && tid == 0) { g_nlight = 0; g_nfull = 0; }
}

// -------- prep: x[B,D,N] -> row-major int8, per-row scale --------
__global__ __launch_bounds__(256) void prep_x_kernel(const float* __restrict__ x) {
    extern __shared__ float xs[];      // [64][516]
    __shared__ float rsx[64];
    int b = blockIdx.y, n0 = blockIdx.x * 64;
    int tid = threadIdx.x;
    const float* xb = x + (size_t)b * D_DIM * N_DIM + n0;
    for (int i = tid; i < 64 * 512; i += 256) {
        int d = i >> 6, nn = i & 63;
        xs[nn * 516 + d] = xb[(size_t)d * N_DIM + nn];
    }
    __syncthreads();
    {
        int row = tid >> 2, q = tid & 3;
        float mx = 0.f;
        for (int d = q; d < 512; d += 4) mx = fmaxf(mx, fabsf(xs[row * 516 + d]));
        mx = fmaxf(mx, __shfl_xor_sync(0xffffffffu, mx, 1));
        mx = fmaxf(mx, __shfl_xor_sync(0xffffffffu, mx, 2));
        if (q == 0) {
            float s = fmaxf(mx, 1e-20f) * (1.0f / 127.0f);
            rsx[row] = 1.0f / s;
            g_sxr[b * N_DIM + n0 + row] = 2.0f * s;   // fold the 2x here
        }
    }
    __syncthreads();
    uint32_t* Aq = g_Aq + (size_t)(b * N_DIM + n0) * 128;
    for (int i = tid; i < 64 * 128; i += 256) {
        int row = i >> 7, w = i & 127;
        float rinv = rsx[row];
        const float* p = xs + row * 516 + w * 4;
        uint32_t pw = (uint32_t)(q8(p[0], rinv) & 0xff)
                    | ((uint32_t)(q8(p[1], rinv) & 0xff) << 8)
                    | ((uint32_t)(q8(p[2], rinv) & 0xff) << 16)
                    | ((uint32_t)(q8(p[3], rinv) & 0xff) << 24);
        Aq[row * 128 + w] = pw;
    }
}

// -------- smem: 3-stage ring, stage = A chunk (16KB) + B chunk (16KB) -------
#define STAGE_BYTES 32768
#define SM_DIST (3 * STAGE_BYTES)   // 98304

// chunk c: nt = c>>2 (B row group), kb = c&3 (128-dim slice)
__device__ __forceinline__ void load_chunk(uint32_t dst, const uint4* Ag,
                                           const uint4* Bg, int c, int tid) {
    const uint4* Bn = Bg + (size_t)(c >> 2) * 4096;
    int kb = c & 3;
    #pragma unroll
    for (int l = 0; l < 4; l++) {
        int i = tid + l * 256;
        int row = i >> 3, ch = i & 7;
        uint32_t soff = (uint32_t)row * 128 + (uint32_t)((ch ^ (row & 7)) << 4);
        size_t goff = (size_t)row * 32 + kb * 8 + ch;
        CP_A16(dst + soff,         Ag + goff);
        CP_A16(dst + 16384 + soff, Bn + goff);
    }
}

// -------- warp-tile compute: 32x64 per warp, 128 dims/chunk, int8 -----------
__device__ __forceinline__ void compute_stage(uint32_t sA, uint32_t sB, int lane,
                                              int wm, int wn, int acc[2][8][4]) {
    #pragma unroll
    for (int kk = 0; kk < 4; kk++) {
        uint32_t ah[2][4];
        #pragma unroll
        for (int i = 0; i < 2; i++) {
            int r = wm * 32 + i * 16 + (lane & 15);
            int c = (kk * 2 + (lane >> 4)) ^ (r & 7);
            ldsm4(ah[i], sA + r * 128 + c * 16);
        }
        #pragma unroll
        for (int j16 = 0; j16 < 4; j16++) {
            int n = wn * 64 + j16 * 16 + (lane & 7) + ((lane >> 4) << 3);
            int c = (kk * 2 + ((lane >> 3) & 1)) ^ (n & 7);
            uint32_t bh[4];
            ldsm4(bh, sB + n * 128 + c * 16);
            #pragma unroll
            for (int i = 0; i < 2; i++) {
                mma16832(acc[i][j16 * 2 + 0], ah[i], bh + 0);
                mma16832(acc[i][j16 * 2 + 1], ah[i], bh + 2);
            }
        }
    }
}

#define INS3(r, s, k) do {                                                        \
    if ((s) > v1[r]) { v3[r] = v2[r]; v2[r] = v1[r]; i2[r] = i1[r];               \
                       v1[r] = (s); i1[r] = (k); }                                \
    else if ((s) > v2[r]) { v3[r] = v2[r]; v2[r] = (s); i2[r] = (k); }            \
    else if ((s) > v3[r]) { v3[r] = (s); }                                        \
} while (0)

// -------- main dist + argmax/classify kernel --------
__global__ void __launch_bounds__(256, 2) vq_dist_kernel(float* __restrict__ out_ind_f) {
    extern __shared__ char smem[];
    uint32_t sb = smem_u32(smem);
    const int tid = threadIdx.x, lane = tid & 31, wid = tid >> 5;
    const int wm = wid & 3, wn = wid >> 2;
    const int m0 = blockIdx.x * 128;
    const uint4* Ag = (const uint4*)(g_Aq + (size_t)m0 * 128);
    const uint4* Bg = (const uint4*)g_Bq;

    // per-thread row scales (2*sx folded already)
    float sxr[4];
    #pragma unroll
    for (int i = 0; i < 2; i++)
        #pragma unroll
        for (int h = 0; h < 2; h++)
            sxr[i * 2 + h] = g_sxr[m0 + wm * 32 + i * 16 + (lane >> 2) + h * 8];

    load_chunk(sb + 0 * STAGE_BYTES, Ag, Bg, 0, tid);
    CP_COMMIT();
    load_chunk(sb + 1 * STAGE_BYTES, Ag, Bg, 1, tid);
    CP_COMMIT();
    int cload = 2;

    float v1[4], v2[4], v3[4];
    int   i1[4], i2[4];
    #pragma unroll
    for (int r = 0; r < 4; r++) {
        v1[r] = v2[r] = v3[r] = -3.0e38f;
        i1[r] = i2[r] = 0;
    }

    for (int nt = 0; nt < 16; nt++) {
        int acc[2][8][4];
        #pragma unroll
        for (int i = 0; i < 2; i++)
            #pragma unroll
            for (int j = 0; j < 8; j++)
                #pragma unroll
                for (int q = 0; q < 4; q++) acc[i][j][q] = 0;

        for (int kb = 0; kb < 4; kb++) {
            int c = nt * 4 + kb;
            if (c == 63) { CP_WAIT(0); } else { CP_WAIT(1); }
            __syncthreads();
            uint32_t slot = sb + (c % 3) * STAGE_BYTES;
            compute_stage(slot, slot + 16384, lane, wm, wn, acc);
            if (cload < 64) {
                load_chunk(sb + (cload % 3) * STAGE_BYTES, Ag, Bg, cload, tid);
                CP_COMMIT();
                cload++;
            }
        }

        #pragma unroll
        for (int j = 0; j < 8; j++) {
            int kb_ = nt * 128 + wn * 64 + j * 8 + (lane & 3) * 2;
            float e2a = g_e2[kb_], e2b = g_e2[kb_ + 1];
            float sea = g_se[kb_], seb = g_se[kb_ + 1];
            #pragma unroll
            for (int i = 0; i < 2; i++) {
                int r0 = i * 2, r1 = i * 2 + 1;
                float s0 = sxr[r0] * sea * (float)acc[i][j][0] - e2a;
                float s1 = sxr[r0] * seb * (float)acc[i][j][1] - e2b;
                float s2 = sxr[r1] * sea * (float)acc[i][j][2] - e2a;
                float s3 = sxr[r1] * seb * (float)acc[i][j][3] - e2b;
                INS3(r0, s0, kb_);
                INS3(r0, s1, kb_ + 1);
                INS3(r1, s2, kb_);
                INS3(r1, s3, kb_ + 1);
            }
        }
    }

    // ---- per-row merge over 8 sources, classify row ----
    float* sV = (float*)smem;                   // [128][8][3]
    int*   sI = (int*)(smem + 128 * 8 * 3 * 4); // [128][8][2]
    __syncthreads();
    #pragma unroll
    for (int r = 0; r < 4; r++) {
        int row = wm * 32 + (r >> 1) * 16 + (r & 1) * 8 + (lane >> 2);
        int src = wn * 4 + (lane & 3);
        float* v = sV + (row * 8 + src) * 3;
        v[0] = v1[r]; v[1] = v2[r]; v[2] = v3[r];
        int* ii = sI + (row * 8 + src) * 2;
        ii[0] = i1[r]; ii[1] = i2[r];
    }
    __syncthreads();
    if (tid < 128) {
        float b1 = -3.0e38f; int bi1 = 0x7fffffff;
        #pragma unroll
        for (int s = 0; s < 8; s++) {
            float v = sV[(tid * 8 + s) * 3];
            int   i = sI[(tid * 8 + s) * 2];
            if (v > b1 || (v == b1 && i < bi1)) { b1 = v; bi1 = i; }
        }
        float thr = b1 - MARGIN;
        int cand[4]; int nc = 0; bool overflow = false;
        #pragma unroll
        for (int s = 0; s < 8; s++) {
            float va = sV[(tid * 8 + s) * 3 + 0];
            float vb = sV[(tid * 8 + s) * 3 + 1];
            float vc = sV[(tid * 8 + s) * 3 + 2];
            int ia = sI[(tid * 8 + s) * 2 + 0];
            int ib = sI[(tid * 8 + s) * 2 + 1];
            if (va >= thr) { if (nc < 4) cand[nc] = ia; nc++; }
            if (vb >= thr) { if (nc < 4) cand[nc] = ib; nc++; }
            if (vc >= thr) overflow = true;
        }
        int m = m0 + tid;
        if (!overflow && nc <= 1) {
            g_ind[m] = bi1;
            out_ind_f[m] = (float)bi1;
        } else if (!overflow && nc <= 4) {
            int slot = atomicAdd(&g_nlight, 1);
            g_lightm[slot] = m;
            #pragma unroll
            for (int c = 0; c < 4; c++) g_cand[(size_t)slot * 4 + c] = (c < nc) ? cand[c] : -1;
        } else {
            int slot = atomicAdd(&g_nfull, 1);
            g_fullm[slot] = m;
        }
    }
}

// -------- light fallback: exact rescore of <=4 candidates, WARP per row -----
__global__ __launch_bounds__(256) void light_kernel(const float* __restrict__ x,
                                                    const float* __restrict__ embed,
                                                    float* __restrict__ out_ind_f) {
    const int nl = g_nlight;
    const int lane = threadIdx.x & 31;
    const int wglob = blockIdx.x * 8 + (threadIdx.x >> 5);
    for (int s = wglob; s < nl; s += gridDim.x * 8) {
        int m = g_lightm[s];
        int b = m >> 13, n = m & (N_DIM - 1);
        const float* xb = x + (size_t)b * D_DIM * N_DIM + n;
        float xr[16];
        #pragma unroll
        for (int j = 0; j < 16; j++)
            xr[j] = xb[(size_t)(lane + 32 * j) * N_DIM];
        float best = -3.0e38f; int bi = 0x7fffffff;
        #pragma unroll
        for (int c = 0; c < 4; c++) {
            int k = g_cand[(size_t)s * 4 + c];
            if (k < 0) break;
            const float* e = embed + (size_t)k * D_DIM;
            float a = 0.f;
            #pragma unroll
            for (int j = 0; j < 16; j++)
                a += xr[j] * e[lane + 32 * j];
            #pragma unroll
            for (int o = 16; o > 0; o >>= 1)
                a += __shfl_xor_sync(0xffffffffu, a, o);
            float sc = 2.f * a - g_e2[k];
            if (sc > best || (sc == best && k < bi)) { best = sc; bi = k; }
        }
        if (lane == 0) { g_ind[m] = bi; out_ind_f[m] = (float)bi; }
    }
}

// -------- full fallback: exact scan of all codewords (rare) --------
__global__ __launch_bounds__(256) void full_kernel(const float* __restrict__ x,
                                                   const float* __restrict__ embed,
                                                   float* __restrict__ out_ind_f) {
    __shared__ float xr[D_DIM];
    __shared__ float bv[256];
    __shared__ int   bI[256];
    int nf = g_nfull;
    for (int f = blockIdx.x; f < nf; f += gridDim.x) {
        int m = g_fullm[f];
        int b = m >> 13, n = m & (N_DIM - 1);
        __syncthreads();
        for (int d = threadIdx.x; d < D_DIM; d += 256)
            xr[d] = x[(size_t)b * D_DIM * N_DIM + (size_t)d * N_DIM + n];
        __syncthreads();
        float best = -3.0e38f; int bi = 0x7fffffff;
        for (int c = 0; c < 8; c++) {
            int k = threadIdx.x + c * 256;
            const float4* er = (const float4*)(embed + (size_t)k * D_DIM);
            float s0 = 0.f, s1 = 0.f, s2 = 0.f, s3 = 0.f;
            #pragma unroll 8
            for (int j = 0; j < 128; j++) {
                float4 e = er[j];
                s0 += xr[4 * j + 0] * e.x;
                s1 += xr[4 * j + 1] * e.y;
                s2 += xr[4 * j + 2] * e.z;
                s3 += xr[4 * j + 3] * e.w;
            }
            float sc = 2.f * ((s0 + s1) + (s2 + s3)) - g_e2[k];
            if (sc > best || (sc == best && k < bi)) { best = sc; bi = k; }
        }
        bv[threadIdx.x] = best; bI[threadIdx.x] = bi;
        __syncthreads();
        for (int o = 128; o > 0; o >>= 1) {
            if (threadIdx.x < o) {
                float ov = bv[threadIdx.x + o]; int oi = bI[threadIdx.x + o];
                if (ov > bv[threadIdx.x] || (ov == bv[threadIdx.x] && oi < bI[threadIdx.x])) {
                    bv[threadIdx.x] = ov; bI[threadIdx.x] = oi;
                }
            }
            __syncthreads();
        }
        if (threadIdx.x == 0) { g_ind[m] = bI[0]; out_ind_f[m] = (float)bI[0]; }
    }
}

// -------- gather: out[b,d,n] = embed[ind[b,n], d] --------
__global__ __launch_bounds__(256) void gather_kernel(const float* __restrict__ embed,
                                                     float* __restrict__ out) {
    extern __shared__ float tile[];
    __shared__ int inds[32];
    const int bb = blockIdx.y;
    const int n0 = blockIdx.x * 32;
    if (threadIdx.x < 32) inds[threadIdx.x] = g_ind[bb * N_DIM + n0 + threadIdx.x];
    __syncthreads();
    for (int i = threadIdx.x; i < 32 * D_DIM; i += 256) {
        int n = i >> 9, d = i & (D_DIM - 1);
        tile[n * 513 + d] = embed[(size_t)inds[n] * D_DIM + d];
    }
    __syncthreads();
    float* obase = out + (size_t)bb * D_DIM * N_DIM + n0;
    for (int i = threadIdx.x; i < 32 * D_DIM; i += 256) {
        int n = i & 31, d = i >> 5;
        obase[(size_t)d * N_DIM + n] = tile[n * 513 + d];
    }
}

// ---------------------------------------------------------------------------
extern "C" void kernel_launch(void* const* d_in, const int* in_sizes, int n_in,
                              void* d_out, int out_size) {
    const float* x     = (const float*)d_in[0];
    const float* embed = (const float*)d_in[1];
    float* out   = (float*)d_out;
    float* out_q = out;
    float* out_i = out + (size_t)B_DIM * D_DIM * N_DIM;
    (void)in_sizes; (void)n_in; (void)out_size;

    static const int gather_smem = 32 * 513 * (int)sizeof(float);
    static const int prepx_smem  = 64 * 516 * (int)sizeof(float);   // 132096
    cudaFuncSetAttribute(gather_kernel, cudaFuncAttributeMaxDynamicSharedMemorySize, gather_smem);
    cudaFuncSetAttribute(prep_x_kernel, cudaFuncAttributeMaxDynamicSharedMemorySize, prepx_smem);
    cudaFuncSetAttribute(vq_dist_kernel, cudaFuncAttributeMaxDynamicSharedMemorySize, SM_DIST);

    prep_embed_kernel<<<K_CB, 128>>>(embed);
    prep_x_kernel<<<dim3(N_DIM / 64, B_DIM), 256, prepx_smem>>>(x);
    vq_dist_kernel<<<M_ROWS / 128, 256, SM_DIST>>>(out_i);
    light_kernel<<<1024, 256>>>(x, embed, out_i);
    full_kernel<<<256, 256>>>(x, embed, out_i);
    gather_kernel<<<dim3(N_DIM / 32, B_DIM), 256, gather_smem>>>(embed, out_q);
}

// round 12
// speedup vs baseline: 1.5614x; 1.5614x over previous
#include <cuda_runtime.h>
#include <cuda_bf16.h>
#include <cstdint>
#include <cstddef>

#define K_CB   2048
#define D_DIM  512
#define B_DIM  16
#define N_DIM  8192
#define M_ROWS (B_DIM * N_DIM)
#define MARGIN 5.0f
#define CAP    12

// -------- device scratch: int8 quantized planes (packed 4 dims/word) --------
__device__ uint32_t g_Aq[(size_t)M_ROWS * 128];
__device__ uint32_t g_Bq[(size_t)K_CB * 128];
__device__ float    g_sxr[M_ROWS];                // 2*sx per row
__device__ float    g_se[K_CB];
__device__ float    g_e2[K_CB];
__device__ int      g_ind[M_ROWS];
__device__ int      g_lightm[M_ROWS];
__device__ int      g_cand[(size_t)M_ROWS * CAP];
__device__ int      g_fullm[M_ROWS];
__device__ int      g_nlight;
__device__ int      g_nfull;

// -------- helpers --------
__device__ __forceinline__ uint32_t smem_u32(const void* p) {
    uint32_t a;
    asm("{ .reg .u64 t; cvta.to.shared.u64 t, %1; cvt.u32.u64 %0, t; }" : "=r"(a) : "l"(p));
    return a;
}
#define CP_A16(s, g) \
    asm volatile("cp.async.cg.shared.global [%0], [%1], 16;" :: "r"(s), "l"(g) : "memory")
#define CP_COMMIT() asm volatile("cp.async.commit_group;" ::: "memory")
#define CP_WAIT(n)  asm volatile("cp.async.wait_group %0;" :: "n"(n) : "memory")

__device__ __forceinline__ void ldsm4(uint32_t* r, uint32_t addr) {
    asm volatile("ldmatrix.sync.aligned.m8n8.x4.shared.b16 {%0,%1,%2,%3}, [%4];"
                 : "=r"(r[0]), "=r"(r[1]), "=r"(r[2]), "=r"(r[3]) : "r"(addr));
}
__device__ __forceinline__ void mma16832(int* c, const uint32_t* a, const uint32_t* b) {
    asm volatile("mma.sync.aligned.m16n8k32.row.col.s32.s8.s8.s32 "
                 "{%0,%1,%2,%3}, {%4,%5,%6,%7}, {%8,%9}, {%0,%1,%2,%3};"
                 : "+r"(c[0]), "+r"(c[1]), "+r"(c[2]), "+r"(c[3])
                 : "r"(a[0]), "r"(a[1]), "r"(a[2]), "r"(a[3]), "r"(b[0]), "r"(b[1]));
}
__device__ __forceinline__ int q8(float v, float rinv) {
    int q = __float2int_rn(v * rinv);
    return max(-127, min(127, q));
}
// ordered-uint encoding for float atomicMax (monotone for all finite floats)
__device__ __forceinline__ unsigned encf(float f) {
    unsigned u = __float_as_uint(f);
    return (u >> 31) ? ~u : (u | 0x80000000u);
}
__device__ __forceinline__ float decf(unsigned u) {
    return (u >> 31) ? __uint_as_float(u & 0x7fffffffu) : __uint_as_float(~u);
}

// -------- prep: codebook quantize + e2 --------
__global__ __launch_bounds__(128) void prep_embed_kernel(const float* __restrict__ embed) {
    __shared__ float er[512];
    __shared__ float wmx[4], wsm[4];
    int k = blockIdx.x;
    const float* row = embed + (size_t)k * D_DIM;
    int tid = threadIdx.x;
    float4 v = ((const float4*)row)[tid];
    ((float4*)er)[tid] = v;
    float mx = fmaxf(fmaxf(fabsf(v.x), fabsf(v.y)), fmaxf(fabsf(v.z), fabsf(v.w)));
    float s2 = v.x * v.x + v.y * v.y + v.z * v.z + v.w * v.w;
    #pragma unroll
    for (int o = 16; o > 0; o >>= 1) {
        mx = fmaxf(mx, __shfl_xor_sync(0xffffffffu, mx, o));
        s2 += __shfl_xor_sync(0xffffffffu, s2, o);
    }
    if ((tid & 31) == 0) { wmx[tid >> 5] = mx; wsm[tid >> 5] = s2; }
    __syncthreads();
    mx = fmaxf(fmaxf(wmx[0], wmx[1]), fmaxf(wmx[2], wmx[3]));
    float e2 = wsm[0] + wsm[1] + wsm[2] + wsm[3];
    float s = fmaxf(mx, 1e-20f) * (1.0f / 127.0f);
    float rinv = 1.0f / s;
    if (tid == 0) { g_se[k] = s; g_e2[k] = e2; }
    const float* p = er + tid * 4;
    uint32_t w = (uint32_t)(q8(p[0], rinv) & 0xff)
               | ((uint32_t)(q8(p[1], rinv) & 0xff) << 8)
               | ((uint32_t)(q8(p[2], rinv) & 0xff) << 16)
               | ((uint32_t)(q8(p[3], rinv) & 0xff) << 24);
    g_Bq[(size_t)k * 128 + tid] = w;
    if (blockIdx.x == 0 && tid == 0) { g_nlight = 0; g_nfull = 0; }
}

// -------- prep: x[B,D,N] -> row-major int8, per-row scale --------
__global__ __launch_bounds__(256) void prep_x_kernel(const float* __restrict__ x) {
    extern __shared__ float xs[];      // [64][516]
    __shared__ float rsx[64];
    int b = blockIdx.y, n0 = blockIdx.x * 64;
    int tid = threadIdx.x;
    const float* xb = x + (size_t)b * D_DIM * N_DIM + n0;
    for (int i = tid; i < 64 * 512; i += 256) {
        int d = i >> 6, nn = i & 63;
        xs[nn * 516 + d] = xb[(size_t)d * N_DIM + nn];
    }
    __syncthreads();
    {
        int row = tid >> 2, q = tid & 3;
        float mx = 0.f;
        for (int d = q; d < 512; d += 4) mx = fmaxf(mx, fabsf(xs[row * 516 + d]));
        mx = fmaxf(mx, __shfl_xor_sync(0xffffffffu, mx, 1));
        mx = fmaxf(mx, __shfl_xor_sync(0xffffffffu, mx, 2));
        if (q == 0) {
            float s = fmaxf(mx, 1e-20f) * (1.0f / 127.0f);
            rsx[row] = 1.0f / s;
            g_sxr[b * N_DIM + n0 + row] = 2.0f * s;
        }
    }
    __syncthreads();
    uint32_t* Aq = g_Aq + (size_t)(b * N_DIM + n0) * 128;
    for (int i = tid; i < 64 * 128; i += 256) {
        int row = i >> 7, w = i & 127;
        float rinv = rsx[row];
        const float* p = xs + row * 516 + w * 4;
        uint32_t pw = (uint32_t)(q8(p[0], rinv) & 0xff)
                    | ((uint32_t)(q8(p[1], rinv) & 0xff) << 8)
                    | ((uint32_t)(q8(p[2], rinv) & 0xff) << 16)
                    | ((uint32_t)(q8(p[3], rinv) & 0xff) << 24);
        Aq[row * 128 + w] = pw;
    }
}

// -------- smem: 3-stage ring, stage = A chunk (16KB) + B chunk (16KB) -------
#define STAGE_BYTES 32768
#define SM_DIST (3 * STAGE_BYTES)   // 98304

__device__ __forceinline__ void load_chunk(uint32_t dst, const uint4* Ag,
                                           const uint4* Bg, int c, int tid) {
    const uint4* Bn = Bg + (size_t)(c >> 2) * 4096;
    int kb = c & 3;
    #pragma unroll
    for (int l = 0; l < 4; l++) {
        int i = tid + l * 256;
        int row = i >> 3, ch = i & 7;
        uint32_t soff = (uint32_t)row * 128 + (uint32_t)((ch ^ (row & 7)) << 4);
        size_t goff = (size_t)row * 32 + kb * 8 + ch;
        CP_A16(dst + soff,         Ag + goff);
        CP_A16(dst + 16384 + soff, Bn + goff);
    }
}

// -------- warp-tile compute: 32x64 per warp, 128 dims/chunk, int8 -----------
__device__ __forceinline__ void compute_stage(uint32_t sA, uint32_t sB, int lane,
                                              int wm, int wn, int acc[2][8][4]) {
    #pragma unroll
    for (int kk = 0; kk < 4; kk++) {
        uint32_t ah[2][4];
        #pragma unroll
        for (int i = 0; i < 2; i++) {
            int r = wm * 32 + i * 16 + (lane & 15);
            int c = (kk * 2 + (lane >> 4)) ^ (r & 7);
            ldsm4(ah[i], sA + r * 128 + c * 16);
        }
        #pragma unroll
        for (int j16 = 0; j16 < 4; j16++) {
            int n = wn * 64 + j16 * 16 + (lane & 7) + ((lane >> 4) << 3);
            int c = (kk * 2 + ((lane >> 3) & 1)) ^ (n & 7);
            uint32_t bh[4];
            ldsm4(bh, sB + n * 128 + c * 16);
            #pragma unroll
            for (int i = 0; i < 2; i++) {
                mma16832(acc[i][j16 * 2 + 0], ah[i], bh + 0);
                mma16832(acc[i][j16 * 2 + 1], ah[i], bh + 2);
            }
        }
    }
}

// -------- main dist + argmax + candidate-collection kernel --------
__global__ void __launch_bounds__(256, 2) vq_dist_kernel(float* __restrict__ out_ind_f) {
    extern __shared__ char smem[];
    __shared__ unsigned rowBestU[128];
    __shared__ int      rowCnt[128];
    __shared__ int      candK[128][CAP];
    __shared__ float    candS[128][CAP];
    uint32_t sb = smem_u32(smem);
    const int tid = threadIdx.x, lane = tid & 31, wid = tid >> 5;
    const int wm = wid & 3, wn = wid >> 2;
    const int m0 = blockIdx.x * 128;
    const uint4* Ag = (const uint4*)(g_Aq + (size_t)m0 * 128);
    const uint4* Bg = (const uint4*)g_Bq;

    if (tid < 128) { rowBestU[tid] = 0u; rowCnt[tid] = 0; }

    // this thread's 4 rows and their scales (2*sx folded)
    int rows[4];
    float sxr[4];
    #pragma unroll
    for (int r = 0; r < 4; r++) {
        rows[r] = wm * 32 + (r >> 1) * 16 + (r & 1) * 8 + (lane >> 2);
        sxr[r] = g_sxr[m0 + rows[r]];
    }

    load_chunk(sb + 0 * STAGE_BYTES, Ag, Bg, 0, tid);
    CP_COMMIT();
    load_chunk(sb + 1 * STAGE_BYTES, Ag, Bg, 1, tid);
    CP_COMMIT();
    int cload = 2;

    for (int nt = 0; nt < 16; nt++) {
        int acc[2][8][4];
        #pragma unroll
        for (int i = 0; i < 2; i++)
            #pragma unroll
            for (int j = 0; j < 8; j++)
                #pragma unroll
                for (int q = 0; q < 4; q++) acc[i][j][q] = 0;

        for (int kb = 0; kb < 4; kb++) {
            int c = nt * 4 + kb;
            if (c == 63) { CP_WAIT(0); } else { CP_WAIT(1); }
            __syncthreads();
            uint32_t slot = sb + (c % 3) * STAGE_BYTES;
            compute_stage(slot, slot + 16384, lane, wm, wn, acc);
            if (cload < 64) {
                load_chunk(sb + (cload % 3) * STAGE_BYTES, Ag, Bg, cload, tid);
                CP_COMMIT();
                cload++;
            }
        }

        // ---- phase 1: per-row maxima for this 128-codeword pass ----
        float lmax[4] = {-3.0e38f, -3.0e38f, -3.0e38f, -3.0e38f};
        #pragma unroll
        for (int j = 0; j < 8; j++) {
            int kb_ = nt * 128 + wn * 64 + j * 8 + (lane & 3) * 2;
            float e2a = g_e2[kb_], e2b = g_e2[kb_ + 1];
            float sea = g_se[kb_], seb = g_se[kb_ + 1];
            #pragma unroll
            for (int i = 0; i < 2; i++) {
                int r0 = i * 2, r1 = i * 2 + 1;
                lmax[r0] = fmaxf(lmax[r0], fmaxf(sxr[r0] * sea * (float)acc[i][j][0] - e2a,
                                                 sxr[r0] * seb * (float)acc[i][j][1] - e2b));
                lmax[r1] = fmaxf(lmax[r1], fmaxf(sxr[r1] * sea * (float)acc[i][j][2] - e2a,
                                                 sxr[r1] * seb * (float)acc[i][j][3] - e2b));
            }
        }
        #pragma unroll
        for (int r = 0; r < 4; r++) {
            lmax[r] = fmaxf(lmax[r], __shfl_xor_sync(0xffffffffu, lmax[r], 1));
            lmax[r] = fmaxf(lmax[r], __shfl_xor_sync(0xffffffffu, lmax[r], 2));
        }
        if ((lane & 3) == 0) {
            #pragma unroll
            for (int r = 0; r < 4; r++)
                atomicMax(&rowBestU[rows[r]], encf(lmax[r]));
        }
        __syncthreads();

        // ---- phase 2: append in-margin candidates (superset-safe) ----
        float thrs[4];
        #pragma unroll
        for (int r = 0; r < 4; r++) thrs[r] = decf(rowBestU[rows[r]]) - MARGIN;
        #pragma unroll
        for (int j = 0; j < 8; j++) {
            int kb_ = nt * 128 + wn * 64 + j * 8 + (lane & 3) * 2;
            float e2a = g_e2[kb_], e2b = g_e2[kb_ + 1];
            float sea = g_se[kb_], seb = g_se[kb_ + 1];
            #pragma unroll
            for (int i = 0; i < 2; i++) {
                int r0 = i * 2, r1 = i * 2 + 1;
                float s0 = sxr[r0] * sea * (float)acc[i][j][0] - e2a;
                float s1 = sxr[r0] * seb * (float)acc[i][j][1] - e2b;
                float s2 = sxr[r1] * sea * (float)acc[i][j][2] - e2a;
                float s3 = sxr[r1] * seb * (float)acc[i][j][3] - e2b;
                if (s0 >= thrs[r0]) {
                    int pos = atomicAdd(&rowCnt[rows[r0]], 1);
                    if (pos < CAP) { candK[rows[r0]][pos] = kb_; candS[rows[r0]][pos] = s0; }
                }
                if (s1 >= thrs[r0]) {
                    int pos = atomicAdd(&rowCnt[rows[r0]], 1);
                    if (pos < CAP) { candK[rows[r0]][pos] = kb_ + 1; candS[rows[r0]][pos] = s1; }
                }
                if (s2 >= thrs[r1]) {
                    int pos = atomicAdd(&rowCnt[rows[r1]], 1);
                    if (pos < CAP) { candK[rows[r1]][pos] = kb_; candS[rows[r1]][pos] = s2; }
                }
                if (s3 >= thrs[r1]) {
                    int pos = atomicAdd(&rowCnt[rows[r1]], 1);
                    if (pos < CAP) { candK[rows[r1]][pos] = kb_ + 1; candS[rows[r1]][pos] = s3; }
                }
            }
        }
    }

    // ---- final classify per row ----
    __syncthreads();
    if (tid < 128) {
        int m = m0 + tid;
        int cnt = rowCnt[tid];
        if (cnt > CAP) {
            int slot = atomicAdd(&g_nfull, 1);
            g_fullm[slot] = m;
        } else {
            float b1 = decf(rowBestU[tid]);
            float thr = b1 - MARGIN;
            int sel[CAP]; int ns = 0;
            for (int c = 0; c < cnt; c++) {
                if (candS[tid][c] >= thr) sel[ns++] = candK[tid][c];
            }
            if (ns <= 1) {
                g_ind[m] = sel[0];
                out_ind_f[m] = (float)sel[0];
            } else {
                int slot = atomicAdd(&g_nlight, 1);
                g_lightm[slot] = m;
                for (int c = 0; c < CAP; c++)
                    g_cand[(size_t)slot * CAP + c] = (c < ns) ? sel[c] : -1;
            }
        }
    }
}

// -------- light fallback: exact rescore of <=CAP candidates, WARP per row ---
__global__ __launch_bounds__(256) void light_kernel(const float* __restrict__ x,
                                                    const float* __restrict__ embed,
                                                    float* __restrict__ out_ind_f) {
    const int nl = g_nlight;
    const int lane = threadIdx.x & 31;
    const int wglob = blockIdx.x * 8 + (threadIdx.x >> 5);
    for (int s = wglob; s < nl; s += gridDim.x * 8) {
        int m = g_lightm[s];
        int b = m >> 13, n = m & (N_DIM - 1);
        const float* xb = x + (size_t)b * D_DIM * N_DIM + n;
        float xr[16];
        #pragma unroll
        for (int j = 0; j < 16; j++)
            xr[j] = xb[(size_t)(lane + 32 * j) * N_DIM];
        float best = -3.0e38f; int bi = 0x7fffffff;
        #pragma unroll 1
        for (int c = 0; c < CAP; c++) {
            int k = g_cand[(size_t)s * CAP + c];
            if (k < 0) break;
            const float* e = embed + (size_t)k * D_DIM;
            float a = 0.f;
            #pragma unroll
            for (int j = 0; j < 16; j++)
                a += xr[j] * e[lane + 32 * j];
            #pragma unroll
            for (int o = 16; o > 0; o >>= 1)
                a += __shfl_xor_sync(0xffffffffu, a, o);
            float sc = 2.f * a - g_e2[k];
            if (sc > best || (sc == best && k < bi)) { best = sc; bi = k; }
        }
        if (lane == 0) { g_ind[m] = bi; out_ind_f[m] = (float)bi; }
    }
}

// -------- full fallback: exact scan of all codewords (rare) --------
__global__ __launch_bounds__(256) void full_kernel(const float* __restrict__ x,
                                                   const float* __restrict__ embed,
                                                   float* __restrict__ out_ind_f) {
    __shared__ float xr[D_DIM];
    __shared__ float bv[256];
    __shared__ int   bI[256];
    int nf = g_nfull;
    for (int f = blockIdx.x; f < nf; f += gridDim.x) {
        int m = g_fullm[f];
        int b = m >> 13, n = m & (N_DIM - 1);
        __syncthreads();
        for (int d = threadIdx.x; d < D_DIM; d += 256)
            xr[d] = x[(size_t)b * D_DIM * N_DIM + (size_t)d * N_DIM + n];
        __syncthreads();
        float best = -3.0e38f; int bi = 0x7fffffff;
        for (int c = 0; c < 8; c++) {
            int k = threadIdx.x + c * 256;
            const float4* er = (const float4*)(embed + (size_t)k * D_DIM);
            float s0 = 0.f, s1 = 0.f, s2 = 0.f, s3 = 0.f;
            #pragma unroll 8
            for (int j = 0; j < 128; j++) {
                float4 e = er[j];
                s0 += xr[4 * j + 0] * e.x;
                s1 += xr[4 * j + 1] * e.y;
                s2 += xr[4 * j + 2] * e.z;
                s3 += xr[4 * j + 3] * e.w;
            }
            float sc = 2.f * ((s0 + s1) + (s2 + s3)) - g_e2[k];
            if (sc > best || (sc == best && k < bi)) { best = sc; bi = k; }
        }
        bv[threadIdx.x] = best; bI[threadIdx.x] = bi;
        __syncthreads();
        for (int o = 128; o > 0; o >>= 1) {
            if (threadIdx.x < o) {
                float ov = bv[threadIdx.x + o]; int oi = bI[threadIdx.x + o];
                if (ov > bv[threadIdx.x] || (ov == bv[threadIdx.x] && oi < bI[threadIdx.x])) {
                    bv[threadIdx.x] = ov; bI[threadIdx.x] = oi;
                }
            }
            __syncthreads();
        }
        if (threadIdx.x == 0) { g_ind[m] = bI[0]; out_ind_f[m] = (float)bI[0]; }
    }
}

// -------- gather: out[b,d,n] = embed[ind[b,n], d] --------
__global__ __launch_bounds__(256) void gather_kernel(const float* __restrict__ embed,
                                                     float* __restrict__ out) {
    extern __shared__ float tile[];
    __shared__ int inds[32];
    const int bb = blockIdx.y;
    const int n0 = blockIdx.x * 32;
    if (threadIdx.x < 32) inds[threadIdx.x] = g_ind[bb * N_DIM + n0 + threadIdx.x];
    __syncthreads();
    for (int i = threadIdx.x; i < 32 * D_DIM; i += 256) {
        int n = i >> 9, d = i & (D_DIM - 1);
        tile[n * 513 + d] = embed[(size_t)inds[n] * D_DIM + d];
    }
    __syncthreads();
    float* obase = out + (size_t)bb * D_DIM * N_DIM + n0;
    for (int i = threadIdx.x; i < 32 * D_DIM; i += 256) {
        int n = i & 31, d = i >> 5;
        obase[(size_t)d * N_DIM + n] = tile[n * 513 + d];
    }
}

// ---------------------------------------------------------------------------
extern "C" void kernel_launch(void* const* d_in, const int* in_sizes, int n_in,
                              void* d_out, int out_size) {
    const float* x     = (const float*)d_in[0];
    const float* embed = (const float*)d_in[1];
    float* out   = (float*)d_out;
    float* out_q = out;
    float* out_i = out + (size_t)B_DIM * D_DIM * N_DIM;
    (void)in_sizes; (void)n_in; (void)out_size;

    static const int gather_smem = 32 * 513 * (int)sizeof(float);
    static const int prepx_smem  = 64 * 516 * (int)sizeof(float);
    cudaFuncSetAttribute(gather_kernel, cudaFuncAttributeMaxDynamicSharedMemorySize, gather_smem);
    cudaFuncSetAttribute(prep_x_kernel, cudaFuncAttributeMaxDynamicSharedMemorySize, prepx_smem);
    cudaFuncSetAttribute(vq_dist_kernel, cudaFuncAttributeMaxDynamicSharedMemorySize, SM_DIST);

    prep_embed_kernel<<<K_CB, 128>>>(embed);
    prep_x_kernel<<<dim3(N_DIM / 64, B_DIM), 256, prepx_smem>>>(x);
    vq_dist_kernel<<<M_ROWS / 128, 256, SM_DIST>>>(out_i);
    light_kernel<<<1024, 256>>>(x, embed, out_i);
    full_kernel<<<256, 256>>>(x, embed, out_i);
    gather_kernel<<<dim3(N_DIM / 32, B_DIM), 256, gather_smem>>>(embed, out_q);
}

// round 13
// speedup vs baseline: 2.6935x; 1.7251x over previous
#include <cuda_runtime.h>
#include <cuda_bf16.h>
#include <cstdint>
#include <cstddef>

#define K_CB   2048
#define D_DIM  512
#define B_DIM  16
#define N_DIM  8192
#define M_ROWS (B_DIM * N_DIM)
#define MARGIN 5.0f
#define CAP    12

// -------- device scratch: int8 quantized planes (packed 4 dims/word) --------
__device__ uint32_t g_Aq[(size_t)M_ROWS * 128];
__device__ uint32_t g_Bq[(size_t)K_CB * 128];
__device__ float    g_sxr[M_ROWS];                // 2*sx per row
__device__ float    g_se[K_CB];
__device__ float    g_e2[K_CB];
__device__ int      g_ind[M_ROWS];
__device__ int      g_lightm[M_ROWS];
__device__ int      g_cand[(size_t)M_ROWS * CAP];
__device__ int      g_fullm[M_ROWS];
__device__ int      g_nlight;
__device__ int      g_nfull;

// -------- helpers --------
__device__ __forceinline__ uint32_t smem_u32(const void* p) {
    uint32_t a;
    asm("{ .reg .u64 t; cvta.to.shared.u64 t, %1; cvt.u32.u64 %0, t; }" : "=r"(a) : "l"(p));
    return a;
}
#define CP_A16(s, g) \
    asm volatile("cp.async.cg.shared.global [%0], [%1], 16;" :: "r"(s), "l"(g) : "memory")
#define CP_COMMIT() asm volatile("cp.async.commit_group;" ::: "memory")
#define CP_WAIT(n)  asm volatile("cp.async.wait_group %0;" :: "n"(n) : "memory")

__device__ __forceinline__ void ldsm4(uint32_t* r, uint32_t addr) {
    asm volatile("ldmatrix.sync.aligned.m8n8.x4.shared.b16 {%0,%1,%2,%3}, [%4];"
                 : "=r"(r[0]), "=r"(r[1]), "=r"(r[2]), "=r"(r[3]) : "r"(addr));
}
__device__ __forceinline__ void mma16832(int* c, const uint32_t* a, const uint32_t* b) {
    asm volatile("mma.sync.aligned.m16n8k32.row.col.s32.s8.s8.s32 "
                 "{%0,%1,%2,%3}, {%4,%5,%6,%7}, {%8,%9}, {%0,%1,%2,%3};"
                 : "+r"(c[0]), "+r"(c[1]), "+r"(c[2]), "+r"(c[3])
                 : "r"(a[0]), "r"(a[1]), "r"(a[2]), "r"(a[3]), "r"(b[0]), "r"(b[1]));
}
__device__ __forceinline__ int q8(float v, float rinv) {
    int q = __float2int_rn(v * rinv);
    return max(-127, min(127, q));
}
// ordered-uint encoding for float atomicMax (monotone for all finite floats)
__device__ __forceinline__ unsigned encf(float f) {
    unsigned u = __float_as_uint(f);
    return (u >> 31) ? ~u : (u | 0x80000000u);
}
__device__ __forceinline__ float decf(unsigned u) {
    return (u >> 31) ? __uint_as_float(u & 0x7fffffffu) : __uint_as_float(~u);
}

// -------- prep: codebook quantize + e2 --------
__global__ __launch_bounds__(128) void prep_embed_kernel(const float* __restrict__ embed) {
    __shared__ float er[512];
    __shared__ float wmx[4], wsm[4];
    int k = blockIdx.x;
    const float* row = embed + (size_t)k * D_DIM;
    int tid = threadIdx.x;
    float4 v = ((const float4*)row)[tid];
    ((float4*)er)[tid] = v;
    float mx = fmaxf(fmaxf(fabsf(v.x), fabsf(v.y)), fmaxf(fabsf(v.z), fabsf(v.w)));
    float s2 = v.x * v.x + v.y * v.y + v.z * v.z + v.w * v.w;
    #pragma unroll
    for (int o = 16; o > 0; o >>= 1) {
        mx = fmaxf(mx, __shfl_xor_sync(0xffffffffu, mx, o));
        s2 += __shfl_xor_sync(0xffffffffu, s2, o);
    }
    if ((tid & 31) == 0) { wmx[tid >> 5] = mx; wsm[tid >> 5] = s2; }
    __syncthreads();
    mx = fmaxf(fmaxf(wmx[0], wmx[1]), fmaxf(wmx[2], wmx[3]));
    float e2 = wsm[0] + wsm[1] + wsm[2] + wsm[3];
    float s = fmaxf(mx, 1e-20f) * (1.0f / 127.0f);
    float rinv = 1.0f / s;
    if (tid == 0) { g_se[k] = s; g_e2[k] = e2; }
    const float* p = er + tid * 4;
    uint32_t w = (uint32_t)(q8(p[0], rinv) & 0xff)
               | ((uint32_t)(q8(p[1], rinv) & 0xff) << 8)
               | ((uint32_t)(q8(p[2], rinv) & 0xff) << 16)
               | ((uint32_t)(q8(p[3], rinv) & 0xff) << 24);
    g_Bq[(size_t)k * 128 + tid] = w;
    if (blockIdx.x == 0 && tid == 0) { g_nlight = 0; g_nfull = 0; }
}

// -------- prep: x[B,D,N] -> row-major int8, per-row scale --------
__global__ __launch_bounds__(256) void prep_x_kernel(const float* __restrict__ x) {
    extern __shared__ float xs[];      // [64][516]
    __shared__ float rsx[64];
    int b = blockIdx.y, n0 = blockIdx.x * 64;
    int tid = threadIdx.x;
    const float* xb = x + (size_t)b * D_DIM * N_DIM + n0;
    for (int i = tid; i < 64 * 512; i += 256) {
        int d = i >> 6, nn = i & 63;
        xs[nn * 516 + d] = xb[(size_t)d * N_DIM + nn];
    }
    __syncthreads();
    {
        int row = tid >> 2, q = tid & 3;
        float mx = 0.f;
        for (int d = q; d < 512; d += 4) mx = fmaxf(mx, fabsf(xs[row * 516 + d]));
        mx = fmaxf(mx, __shfl_xor_sync(0xffffffffu, mx, 1));
        mx = fmaxf(mx, __shfl_xor_sync(0xffffffffu, mx, 2));
        if (q == 0) {
            float s = fmaxf(mx, 1e-20f) * (1.0f / 127.0f);
            rsx[row] = 1.0f / s;
            g_sxr[b * N_DIM + n0 + row] = 2.0f * s;
        }
    }
    __syncthreads();
    uint32_t* Aq = g_Aq + (size_t)(b * N_DIM + n0) * 128;
    for (int i = tid; i < 64 * 128; i += 256) {
        int row = i >> 7, w = i & 127;
        float rinv = rsx[row];
        const float* p = xs + row * 516 + w * 4;
        uint32_t pw = (uint32_t)(q8(p[0], rinv) & 0xff)
                    | ((uint32_t)(q8(p[1], rinv) & 0xff) << 8)
                    | ((uint32_t)(q8(p[2], rinv) & 0xff) << 16)
                    | ((uint32_t)(q8(p[3], rinv) & 0xff) << 24);
        Aq[row * 128 + w] = pw;
    }
}

// -------- smem: 3-stage ring, stage = A chunk (16KB) + B chunk (16KB) -------
#define STAGE_BYTES 32768
#define SM_DIST (3 * STAGE_BYTES)   // 98304

__device__ __forceinline__ void load_chunk(uint32_t dst, const uint4* Ag,
                                           const uint4* Bg, int c, int tid) {
    const uint4* Bn = Bg + (size_t)(c >> 2) * 4096;
    int kb = c & 3;
    #pragma unroll
    for (int l = 0; l < 4; l++) {
        int i = tid + l * 256;
        int row = i >> 3, ch = i & 7;
        uint32_t soff = (uint32_t)row * 128 + (uint32_t)((ch ^ (row & 7)) << 4);
        size_t goff = (size_t)row * 32 + kb * 8 + ch;
        CP_A16(dst + soff,         Ag + goff);
        CP_A16(dst + 16384 + soff, Bn + goff);
    }
}

// -------- warp-tile compute: 32x64 per warp, 128 dims/chunk, int8 -----------
__device__ __forceinline__ void compute_stage(uint32_t sA, uint32_t sB, int lane,
                                              int wm, int wn, int acc[2][8][4]) {
    #pragma unroll
    for (int kk = 0; kk < 4; kk++) {
        uint32_t ah[2][4];
        #pragma unroll
        for (int i = 0; i < 2; i++) {
            int r = wm * 32 + i * 16 + (lane & 15);
            int c = (kk * 2 + (lane >> 4)) ^ (r & 7);
            ldsm4(ah[i], sA + r * 128 + c * 16);
        }
        #pragma unroll
        for (int j16 = 0; j16 < 4; j16++) {
            int n = wn * 64 + j16 * 16 + (lane & 7) + ((lane >> 4) << 3);
            int c = (kk * 2 + ((lane >> 3) & 1)) ^ (n & 7);
            uint32_t bh[4];
            ldsm4(bh, sB + n * 128 + c * 16);
            #pragma unroll
            for (int i = 0; i < 2; i++) {
                mma16832(acc[i][j16 * 2 + 0], ah[i], bh + 0);
                mma16832(acc[i][j16 * 2 + 1], ah[i], bh + 2);
            }
        }
    }
}

// -------- main dist + argmax + candidate-collection kernel --------
__global__ void __launch_bounds__(256, 2) vq_dist_kernel(float* __restrict__ out_ind_f) {
    extern __shared__ char smem[];
    __shared__ unsigned rowBestU[128];
    __shared__ int      rowCnt[128];
    __shared__ int      rowOvf[128];
    __shared__ int      candK[128][CAP];
    __shared__ float    candS[128][CAP];
    uint32_t sb = smem_u32(smem);
    const int tid = threadIdx.x, lane = tid & 31, wid = tid >> 5;
    const int wm = wid & 3, wn = wid >> 2;
    const int m0 = blockIdx.x * 128;
    const uint4* Ag = (const uint4*)(g_Aq + (size_t)m0 * 128);
    const uint4* Bg = (const uint4*)g_Bq;

    if (tid < 128) { rowBestU[tid] = 0u; rowCnt[tid] = 0; rowOvf[tid] = 0; }

    int rows[4];
    float sxr[4];
    #pragma unroll
    for (int r = 0; r < 4; r++) {
        rows[r] = wm * 32 + (r >> 1) * 16 + (r & 1) * 8 + (lane >> 2);
        sxr[r] = g_sxr[m0 + rows[r]];
    }

    load_chunk(sb + 0 * STAGE_BYTES, Ag, Bg, 0, tid);
    CP_COMMIT();
    load_chunk(sb + 1 * STAGE_BYTES, Ag, Bg, 1, tid);
    CP_COMMIT();
    int cload = 2;

    for (int nt = 0; nt < 16; nt++) {
        int acc[2][8][4];
        #pragma unroll
        for (int i = 0; i < 2; i++)
            #pragma unroll
            for (int j = 0; j < 8; j++)
                #pragma unroll
                for (int q = 0; q < 4; q++) acc[i][j][q] = 0;

        for (int kb = 0; kb < 4; kb++) {
            int c = nt * 4 + kb;
            if (c == 63) { CP_WAIT(0); } else { CP_WAIT(1); }
            __syncthreads();
            uint32_t slot = sb + (c % 3) * STAGE_BYTES;
            compute_stage(slot, slot + 16384, lane, wm, wn, acc);
            if (cload < 64) {
                load_chunk(sb + (cload % 3) * STAGE_BYTES, Ag, Bg, cload, tid);
                CP_COMMIT();
                cload++;
            }
        }

        // ---- phase 1: per-row maxima for this 128-codeword pass ----
        float lmax[4] = {-3.0e38f, -3.0e38f, -3.0e38f, -3.0e38f};
        #pragma unroll
        for (int j = 0; j < 8; j++) {
            int kb_ = nt * 128 + wn * 64 + j * 8 + (lane & 3) * 2;
            float e2a = g_e2[kb_], e2b = g_e2[kb_ + 1];
            float sea = g_se[kb_], seb = g_se[kb_ + 1];
            #pragma unroll
            for (int i = 0; i < 2; i++) {
                int r0 = i * 2, r1 = i * 2 + 1;
                lmax[r0] = fmaxf(lmax[r0], fmaxf(sxr[r0] * sea * (float)acc[i][j][0] - e2a,
                                                 sxr[r0] * seb * (float)acc[i][j][1] - e2b));
                lmax[r1] = fmaxf(lmax[r1], fmaxf(sxr[r1] * sea * (float)acc[i][j][2] - e2a,
                                                 sxr[r1] * seb * (float)acc[i][j][3] - e2b));
            }
        }
        #pragma unroll
        for (int r = 0; r < 4; r++) {
            lmax[r] = fmaxf(lmax[r], __shfl_xor_sync(0xffffffffu, lmax[r], 1));
            lmax[r] = fmaxf(lmax[r], __shfl_xor_sync(0xffffffffu, lmax[r], 2));
        }
        if ((lane & 3) == 0) {
            #pragma unroll
            for (int r = 0; r < 4; r++)
                atomicMax(&rowBestU[rows[r]], encf(lmax[r]));
        }
        __syncthreads();

        // ---- phase 1.5: compact buffer against the updated best ----
        if (tid < 128) {
            float thr = decf(rowBestU[tid]) - MARGIN;
            int cnt = min(rowCnt[tid], CAP);
            int w = 0;
            for (int c = 0; c < cnt; c++) {
                if (candS[tid][c] >= thr) {
                    candK[tid][w] = candK[tid][c];
                    candS[tid][w] = candS[tid][c];
                    w++;
                }
            }
            if (rowCnt[tid] > CAP) rowOvf[tid] = 1;   // lost appends -> full
            rowCnt[tid] = w;
        }
        __syncthreads();

        // ---- phase 2: append in-margin candidates (superset-safe) ----
        float thrs[4];
        #pragma unroll
        for (int r = 0; r < 4; r++) thrs[r] = decf(rowBestU[rows[r]]) - MARGIN;
        #pragma unroll
        for (int j = 0; j < 8; j++) {
            int kb_ = nt * 128 + wn * 64 + j * 8 + (lane & 3) * 2;
            float e2a = g_e2[kb_], e2b = g_e2[kb_ + 1];
            float sea = g_se[kb_], seb = g_se[kb_ + 1];
            #pragma unroll
            for (int i = 0; i < 2; i++) {
                int r0 = i * 2, r1 = i * 2 + 1;
                float s0 = sxr[r0] * sea * (float)acc[i][j][0] - e2a;
                float s1 = sxr[r0] * seb * (float)acc[i][j][1] - e2b;
                float s2 = sxr[r1] * sea * (float)acc[i][j][2] - e2a;
                float s3 = sxr[r1] * seb * (float)acc[i][j][3] - e2b;
                if (s0 >= thrs[r0]) {
                    int pos = atomicAdd(&rowCnt[rows[r0]], 1);
                    if (pos < CAP) { candK[rows[r0]][pos] = kb_; candS[rows[r0]][pos] = s0; }
                }
                if (s1 >= thrs[r0]) {
                    int pos = atomicAdd(&rowCnt[rows[r0]], 1);
                    if (pos < CAP) { candK[rows[r0]][pos] = kb_ + 1; candS[rows[r0]][pos] = s1; }
                }
                if (s2 >= thrs[r1]) {
                    int pos = atomicAdd(&rowCnt[rows[r1]], 1);
                    if (pos < CAP) { candK[rows[r1]][pos] = kb_; candS[rows[r1]][pos] = s2; }
                }
                if (s3 >= thrs[r1]) {
                    int pos = atomicAdd(&rowCnt[rows[r1]], 1);
                    if (pos < CAP) { candK[rows[r1]][pos] = kb_ + 1; candS[rows[r1]][pos] = s3; }
                }
            }
        }
    }

    // ---- final classify per row ----
    __syncthreads();
    if (tid < 128) {
        int m = m0 + tid;
        int cnt = rowCnt[tid];
        if (rowOvf[tid] || cnt > CAP) {
            int slot = atomicAdd(&g_nfull, 1);
            g_fullm[slot] = m;
        } else {
            float thr = decf(rowBestU[tid]) - MARGIN;
            int sel[CAP]; int ns = 0;
            for (int c = 0; c < cnt; c++) {
                if (candS[tid][c] >= thr) sel[ns++] = candK[tid][c];
            }
            if (ns <= 1) {
                g_ind[m] = sel[0];
                out_ind_f[m] = (float)sel[0];
            } else {
                int slot = atomicAdd(&g_nlight, 1);
                g_lightm[slot] = m;
                for (int c = 0; c < CAP; c++)
                    g_cand[(size_t)slot * CAP + c] = (c < ns) ? sel[c] : -1;
            }
        }
    }
}

// -------- light fallback: exact rescore of <=CAP candidates, WARP per row ---
__global__ __launch_bounds__(256) void light_kernel(const float* __restrict__ x,
                                                    const float* __restrict__ embed,
                                                    float* __restrict__ out_ind_f) {
    const int nl = g_nlight;
    const int lane = threadIdx.x & 31;
    const int wglob = blockIdx.x * 8 + (threadIdx.x >> 5);
    for (int s = wglob; s < nl; s += gridDim.x * 8) {
        int m = g_lightm[s];
        int b = m >> 13, n = m & (N_DIM - 1);
        const float* xb = x + (size_t)b * D_DIM * N_DIM + n;
        float xr[16];
        #pragma unroll
        for (int j = 0; j < 16; j++)
            xr[j] = xb[(size_t)(lane + 32 * j) * N_DIM];
        float best = -3.0e38f; int bi = 0x7fffffff;
        #pragma unroll 1
        for (int c = 0; c < CAP; c++) {
            int k = g_cand[(size_t)s * CAP + c];
            if (k < 0) break;
            const float* e = embed + (size_t)k * D_DIM;
            float a = 0.f;
            #pragma unroll
            for (int j = 0; j < 16; j++)
                a += xr[j] * e[lane + 32 * j];
            #pragma unroll
            for (int o = 16; o > 0; o >>= 1)
                a += __shfl_xor_sync(0xffffffffu, a, o);
            float sc = 2.f * a - g_e2[k];
            if (sc > best || (sc == best && k < bi)) { best = sc; bi = k; }
        }
        if (lane == 0) { g_ind[m] = bi; out_ind_f[m] = (float)bi; }
    }
}

// -------- full fallback: exact scan of all codewords (rare) --------
__global__ __launch_bounds__(256) void full_kernel(const float* __restrict__ x,
                                                   const float* __restrict__ embed,
                                                   float* __restrict__ out_ind_f) {
    __shared__ float xr[D_DIM];
    __shared__ float bv[256];
    __shared__ int   bI[256];
    int nf = g_nfull;
    for (int f = blockIdx.x; f < nf; f += gridDim.x) {
        int m = g_fullm[f];
        int b = m >> 13, n = m & (N_DIM - 1);
        __syncthreads();
        for (int d = threadIdx.x; d < D_DIM; d += 256)
            xr[d] = x[(size_t)b * D_DIM * N_DIM + (size_t)d * N_DIM + n];
        __syncthreads();
        float best = -3.0e38f; int bi = 0x7fffffff;
        for (int c = 0; c < 8; c++) {
            int k = threadIdx.x + c * 256;
            const float4* er = (const float4*)(embed + (size_t)k * D_DIM);
            float s0 = 0.f, s1 = 0.f, s2 = 0.f, s3 = 0.f;
            #pragma unroll 8
            for (int j = 0; j < 128; j++) {
                float4 e = er[j];
                s0 += xr[4 * j + 0] * e.x;
                s1 += xr[4 * j + 1] * e.y;
                s2 += xr[4 * j + 2] * e.z;
                s3 += xr[4 * j + 3] * e.w;
            }
            float sc = 2.f * ((s0 + s1) + (s2 + s3)) - g_e2[k];
            if (sc > best || (sc == best && k < bi)) { best = sc; bi = k; }
        }
        bv[threadIdx.x] = best; bI[threadIdx.x] = bi;
        __syncthreads();
        for (int o = 128; o > 0; o >>= 1) {
            if (threadIdx.x < o) {
                float ov = bv[threadIdx.x + o]; int oi = bI[threadIdx.x + o];
                if (ov > bv[threadIdx.x] || (ov == bv[threadIdx.x] && oi < bI[threadIdx.x])) {
                    bv[threadIdx.x] = ov; bI[threadIdx.x] = oi;
                }
            }
            __syncthreads();
        }
        if (threadIdx.x == 0) { g_ind[m] = bI[0]; out_ind_f[m] = (float)bI[0]; }
    }
}

// -------- gather: out[b,d,n] = embed[ind[b,n], d] --------
__global__ __launch_bounds__(256) void gather_kernel(const float* __restrict__ embed,
                                                     float* __restrict__ out) {
    extern __shared__ float tile[];
    __shared__ int inds[32];
    const int bb = blockIdx.y;
    const int n0 = blockIdx.x * 32;
    if (threadIdx.x < 32) inds[threadIdx.x] = g_ind[bb * N_DIM + n0 + threadIdx.x];
    __syncthreads();
    for (int i = threadIdx.x; i < 32 * D_DIM; i += 256) {
        int n = i >> 9, d = i & (D_DIM - 1);
        tile[n * 513 + d] = embed[(size_t)inds[n] * D_DIM + d];
    }
    __syncthreads();
    float* obase = out + (size_t)bb * D_DIM * N_DIM + n0;
    for (int i = threadIdx.x; i < 32 * D_DIM; i += 256) {
        int n = i & 31, d = i >> 5;
        obase[(size_t)d * N_DIM + n] = tile[n * 513 + d];
    }
}

// ---------------------------------------------------------------------------
extern "C" void kernel_launch(void* const* d_in, const int* in_sizes, int n_in,
                              void* d_out, int out_size) {
    const float* x     = (const float*)d_in[0];
    const float* embed = (const float*)d_in[1];
    float* out   = (float*)d_out;
    float* out_q = out;
    float* out_i = out + (size_t)B_DIM * D_DIM * N_DIM;
    (void)in_sizes; (void)n_in; (void)out_size;

    static const int gather_smem = 32 * 513 * (int)sizeof(float);
    static const int prepx_smem  = 64 * 516 * (int)sizeof(float);
    cudaFuncSetAttribute(gather_kernel, cudaFuncAttributeMaxDynamicSharedMemorySize, gather_smem);
    cudaFuncSetAttribute(prep_x_kernel, cudaFuncAttributeMaxDynamicSharedMemorySize, prepx_smem);
    cudaFuncSetAttribute(vq_dist_kernel, cudaFuncAttributeMaxDynamicSharedMemorySize, SM_DIST);

    prep_embed_kernel<<<K_CB, 128>>>(embed);
    prep_x_kernel<<<dim3(N_DIM / 64, B_DIM), 256, prepx_smem>>>(x);
    vq_dist_kernel<<<M_ROWS / 128, 256, SM_DIST>>>(out_i);
    light_kernel<<<1024, 256>>>(x, embed, out_i);
    full_kernel<<<256, 256>>>(x, embed, out_i);
    gather_kernel<<<dim3(N_DIM / 32, B_DIM), 256, gather_smem>>>(embed, out_q);
}

// round 14
// speedup vs baseline: 5.0773x; 1.8850x over previous
#include <cuda_runtime.h>
#include <cuda_bf16.h>
#include <cstdint>
#include <cstddef>

#define K_CB   2048
#define D_DIM  512
#define B_DIM  16
#define N_DIM  8192
#define M_ROWS (B_DIM * N_DIM)
#define MARGIN 1.0f

// -------- device scratch: hi bf16 plane only, packed in dim-pairs -----------
__device__ uint32_t g_Ah[(size_t)M_ROWS * 256];
__device__ uint32_t g_Bh[(size_t)K_CB * 256];
__device__ float    g_e2[K_CB];
__device__ int      g_ind[M_ROWS];               // approx argmax from dist
__device__ int      g_lightm[M_ROWS];
__device__ int      g_cand[(size_t)M_ROWS * 4];
__device__ int      g_fullm[M_ROWS];
__device__ int      g_nlight;
__device__ int      g_nfull;

// -------- helpers --------
__device__ __forceinline__ uint32_t smem_u32(const void* p) {
    uint32_t a;
    asm("{ .reg .u64 t; cvta.to.shared.u64 t, %1; cvt.u32.u64 %0, t; }" : "=r"(a) : "l"(p));
    return a;
}
#define CP_A16(s, g) \
    asm volatile("cp.async.cg.shared.global [%0], [%1], 16;" :: "r"(s), "l"(g) : "memory")
#define CP_COMMIT() asm volatile("cp.async.commit_group;" ::: "memory")
#define CP_WAIT(n)  asm volatile("cp.async.wait_group %0;" :: "n"(n) : "memory")

__device__ __forceinline__ void ldsm4(uint32_t* r, uint32_t addr) {
    asm volatile("ldmatrix.sync.aligned.m8n8.x4.shared.b16 {%0,%1,%2,%3}, [%4];"
                 : "=r"(r[0]), "=r"(r[1]), "=r"(r[2]), "=r"(r[3]) : "r"(addr));
}
__device__ __forceinline__ void mma16816(float* c, const uint32_t* a, const uint32_t* b) {
    asm volatile("mma.sync.aligned.m16n8k16.row.col.f32.bf16.bf16.f32 "
                 "{%0,%1,%2,%3}, {%4,%5,%6,%7}, {%8,%9}, {%0,%1,%2,%3};"
                 : "+f"(c[0]), "+f"(c[1]), "+f"(c[2]), "+f"(c[3])
                 : "r"(a[0]), "r"(a[1]), "r"(a[2]), "r"(a[3]), "r"(b[0]), "r"(b[1]));
}
__device__ __forceinline__ uint32_t bf16hi(float v) {
    return (uint32_t)__bfloat16_as_ushort(__float2bfloat16(v));
}

// -------- prep: codebook hi plane + e2 --------
__global__ __launch_bounds__(128) void prep_embed_kernel(const float* __restrict__ embed) {
    int k = blockIdx.x;
    const float* row = embed + (size_t)k * D_DIM;
    uint32_t* bh = g_Bh + (size_t)k * 256;
    float s = 0.f;
    for (int j = threadIdx.x; j < 256; j += 128) {
        float v0 = row[2 * j], v1 = row[2 * j + 1];
        s += v0 * v0 + v1 * v1;
        bh[j] = bf16hi(v0) | (bf16hi(v1) << 16);
    }
    #pragma unroll
    for (int o = 16; o > 0; o >>= 1) s += __shfl_down_sync(0xffffffffu, s, o);
    __shared__ float ws[4];
    if ((threadIdx.x & 31) == 0) ws[threadIdx.x >> 5] = s;
    __syncthreads();
    if (threadIdx.x == 0) g_e2[k] = ws[0] + ws[1] + ws[2] + ws[3];
    if (blockIdx.x == 0 && threadIdx.x == 0) { g_nlight = 0; g_nfull = 0; }
}

// -------- prep: x[B,D,N] -> row-major hi plane (transpose through smem) -----
__global__ __launch_bounds__(256) void prep_x_kernel(const float* __restrict__ x) {
    __shared__ uint16_t t[64][66];
    int b = blockIdx.y, n0 = blockIdx.x * 64;
    const float* xb = x + (size_t)b * D_DIM * N_DIM + n0;
    for (int dc = 0; dc < 8; dc++) {
        __syncthreads();
        #pragma unroll
        for (int l = 0; l < 16; l++) {
            int i = threadIdx.x + l * 256;
            int dd = i >> 6, nn = i & 63;
            t[dd][nn] = (uint16_t)bf16hi(xb[(size_t)(dc * 64 + dd) * N_DIM + nn]);
        }
        __syncthreads();
        #pragma unroll
        for (int l = 0; l < 8; l++) {
            int i = threadIdx.x + l * 256;
            int nn = i >> 5, jj = i & 31;
            uint32_t p = (uint32_t)t[2 * jj][nn] | ((uint32_t)t[2 * jj + 1][nn] << 16);
            g_Ah[(size_t)(b * N_DIM + n0 + nn) * 256 + dc * 32 + jj] = p;
        }
    }
}

// -------- smem: 2-stage ring, stage = A chunk (16KB) + B chunk (16KB) -------
#define STAGE_BYTES 32768
#define SM_DIST 98304          // 96 KB dynamic: ring (2x32KB) + epilogue reuse

__device__ __forceinline__ void load_tiles(uint32_t ss, const uint4* Ah,
                                           const uint4* Bh, int kb, int tid) {
    #pragma unroll
    for (int l = 0; l < 4; l++) {
        int i = tid + l * 256;
        int row = i >> 3, ch = i & 7;
        uint32_t soff = (uint32_t)row * 128 + (uint32_t)((ch ^ (row & 7)) << 4);
        size_t goff = (size_t)row * 64 + (size_t)kb * 8 + ch;
        CP_A16(ss + soff,         Ah + goff);
        CP_A16(ss + 16384 + soff, Bh + goff);
    }
}

// -------- warp-tile compute: 32x64 per warp, 64 dims/stage, hi x hi ---------
__device__ __forceinline__ void compute_stage(uint32_t ss, int lane, int wm, int wn,
                                              float acc[2][8][4]) {
    uint32_t sAh = ss, sBh = ss + 16384;
    #pragma unroll
    for (int kk = 0; kk < 4; kk++) {
        uint32_t ah[2][4];
        #pragma unroll
        for (int i = 0; i < 2; i++) {
            int r = wm * 32 + i * 16 + (lane & 15);
            int c = (kk * 2 + (lane >> 4)) ^ (r & 7);
            ldsm4(ah[i], sAh + r * 128 + c * 16);
        }
        #pragma unroll
        for (int j16 = 0; j16 < 4; j16++) {
            int n = wn * 64 + j16 * 16 + (lane & 7) + ((lane >> 4) << 3);
            int c = (kk * 2 + ((lane >> 3) & 1)) ^ (n & 7);
            uint32_t bh[4];
            ldsm4(bh, sBh + n * 128 + c * 16);
            #pragma unroll
            for (int i = 0; i < 2; i++) {
                mma16816(acc[i][j16 * 2 + 0], ah[i], bh + 0);
                mma16816(acc[i][j16 * 2 + 1], ah[i], bh + 2);
            }
        }
    }
}

#define INS3(r, s, k) do {                                                        \
    if ((s) > v1[r]) { v3[r] = v2[r]; v2[r] = v1[r]; i2[r] = i1[r];               \
                       v1[r] = (s); i1[r] = (k); }                                \
    else if ((s) > v2[r]) { v3[r] = v2[r]; v2[r] = (s); i2[r] = (k); }            \
    else if ((s) > v3[r]) { v3[r] = (s); }                                        \
} while (0)

// -------- main dist + argmax/classify + fused gather kernel --------
__global__ void __launch_bounds__(256, 2) vq_dist_kernel(const float* __restrict__ embed,
                                                         float* __restrict__ out_q,
                                                         float* __restrict__ out_ind_f) {
    extern __shared__ char smem[];
    __shared__ float sB1[2][128];
    __shared__ float sB2[2][128];
    __shared__ int   sIx[2][128];
    __shared__ int   finIdx[128];
    uint32_t sb = smem_u32(smem);
    const int tid = threadIdx.x, lane = tid & 31, wid = tid >> 5;
    const int wm = wid & 3, wn = wid >> 2;
    const int m0 = blockIdx.x * 128;
    const uint4* Ah = (const uint4*)(g_Ah + (size_t)m0 * 256);

    float v1[4], v2[4], v3[4];
    int   i1[4], i2[4];
    #pragma unroll
    for (int r = 0; r < 4; r++) {
        v1[r] = v2[r] = v3[r] = -3.0e38f;
        i1[r] = i2[r] = 0;
    }

    for (int nt = 0; nt < 16; nt++) {
        const uint4* Bh = (const uint4*)(g_Bh + (size_t)nt * 128 * 256);

        float acc[2][8][4];
        #pragma unroll
        for (int i = 0; i < 2; i++)
            #pragma unroll
            for (int j = 0; j < 8; j++)
                #pragma unroll
                for (int q = 0; q < 4; q++) acc[i][j][q] = 0.f;

        load_tiles(sb, Ah, Bh, 0, tid);
        CP_COMMIT();
        for (int kb = 0; kb < 8; kb++) {
            uint32_t cur = sb + (kb & 1) * STAGE_BYTES;
            if (kb < 7) {
                load_tiles(sb + ((kb + 1) & 1) * STAGE_BYTES, Ah, Bh, kb + 1, tid);
                CP_COMMIT();
                CP_WAIT(1);
            } else {
                CP_WAIT(0);
            }
            __syncthreads();
            compute_stage(cur, lane, wm, wn, acc);
            __syncthreads();
        }

        #pragma unroll
        for (int j = 0; j < 8; j++) {
            int kb_ = nt * 128 + wn * 64 + j * 8 + (lane & 3) * 2;
            float e2a = g_e2[kb_], e2b = g_e2[kb_ + 1];
            #pragma unroll
            for (int i = 0; i < 2; i++) {
                float s0 = 2.f * acc[i][j][0] - e2a;
                float s1 = 2.f * acc[i][j][1] - e2b;
                float s2 = 2.f * acc[i][j][2] - e2a;
                float s3 = 2.f * acc[i][j][3] - e2b;
                int r0 = i * 2, r1 = i * 2 + 1;
                INS3(r0, s0, kb_);
                INS3(r0, s1, kb_ + 1);
                INS3(r1, s2, kb_);
                INS3(r1, s3, kb_ + 1);
            }
        }
    }

    // ---- per-row merge over 8 sources, classify row ----
    float* sV = (float*)smem;                   // [128][8][3]
    int*   sI = (int*)(smem + 128 * 8 * 3 * 4); // [128][8][2]
    __syncthreads();
    #pragma unroll
    for (int r = 0; r < 4; r++) {
        int row = wm * 32 + (r >> 1) * 16 + (r & 1) * 8 + (lane >> 2);
        int src = wn * 4 + (lane & 3);
        float* v = sV + (row * 8 + src) * 3;
        v[0] = v1[r]; v[1] = v2[r]; v[2] = v3[r];
        int* ii = sI + (row * 8 + src) * 2;
        ii[0] = i1[r]; ii[1] = i2[r];
    }
    __syncthreads();
    if (tid < 128) {
        float b1 = -3.0e38f; int bi1 = 0x7fffffff;
        #pragma unroll
        for (int s = 0; s < 8; s++) {
            float v = sV[(tid * 8 + s) * 3];
            int   i = sI[(tid * 8 + s) * 2];
            if (v > b1 || (v == b1 && i < bi1)) { b1 = v; bi1 = i; }
        }
        float thr = b1 - MARGIN;
        int cand[4]; int nc = 0; bool overflow = false;
        #pragma unroll
        for (int s = 0; s < 8; s++) {
            float va = sV[(tid * 8 + s) * 3 + 0];
            float vb = sV[(tid * 8 + s) * 3 + 1];
            float vc = sV[(tid * 8 + s) * 3 + 2];
            int ia = sI[(tid * 8 + s) * 2 + 0];
            int ib = sI[(tid * 8 + s) * 2 + 1];
            if (va >= thr) { if (nc < 4) cand[nc] = ia; nc++; }
            if (vb >= thr) { if (nc < 4) cand[nc] = ib; nc++; }
            if (vc >= thr) overflow = true;
        }
        int m = m0 + tid;
        // always publish the approx best; fallbacks patch on change
        finIdx[tid] = bi1;
        g_ind[m] = bi1;
        out_ind_f[m] = (float)bi1;
        if (!overflow && nc > 1 && nc <= 4) {
            int slot = atomicAdd(&g_nlight, 1);
            g_lightm[slot] = m;
            #pragma unroll
            for (int c = 0; c < 4; c++) g_cand[(size_t)slot * 4 + c] = (c < nc) ? cand[c] : -1;
        } else if (overflow || nc > 4) {
            int slot = atomicAdd(&g_nfull, 1);
            g_fullm[slot] = m;
        }
    }
    __syncthreads();

    // ---- fused gather: out_q[b][d][n0+row] = embed[finIdx[row]][d] ----
    {
        const int b = m0 >> 13;            // N_DIM = 8192
        const int n0 = m0 & (N_DIM - 1);
        float* tile = (float*)smem;        // [32][513] = 65.7 KB, reuse ring
        float* obase = out_q + (size_t)b * D_DIM * N_DIM + n0;
        for (int sub = 0; sub < 4; sub++) {
            __syncthreads();
            for (int i = tid; i < 32 * D_DIM; i += 256) {
                int rr = i >> 9, d = i & (D_DIM - 1);
                tile[rr * 513 + d] = embed[(size_t)finIdx[sub * 32 + rr] * D_DIM + d];
            }
            __syncthreads();
            for (int i = tid; i < 32 * D_DIM; i += 256) {
                int rr = i & 31, d = i >> 5;
                obase[(size_t)d * N_DIM + sub * 32 + rr] = tile[rr * 513 + d];
            }
        }
    }
}

// -------- light fallback: exact rescore of <=4 candidates, patch on change --
__global__ __launch_bounds__(256) void light_kernel(const float* __restrict__ x,
                                                    const float* __restrict__ embed,
                                                    float* __restrict__ out_q,
                                                    float* __restrict__ out_ind_f) {
    const int nl = g_nlight;
    const int lane = threadIdx.x & 31;
    const int wglob = blockIdx.x * 8 + (threadIdx.x >> 5);
    for (int s = wglob; s < nl; s += gridDim.x * 8) {
        int m = g_lightm[s];
        int b = m >> 13, n = m & (N_DIM - 1);
        const float* xb = x + (size_t)b * D_DIM * N_DIM + n;
        float xr[16];
        #pragma unroll
        for (int j = 0; j < 16; j++)
            xr[j] = xb[(size_t)(lane + 32 * j) * N_DIM];
        float best = -3.0e38f; int bi = 0x7fffffff;
        #pragma unroll
        for (int c = 0; c < 4; c++) {
            int k = g_cand[(size_t)s * 4 + c];
            if (k < 0) break;                       // uniform across warp
            const float* e = embed + (size_t)k * D_DIM;
            float a = 0.f;
            #pragma unroll
            for (int j = 0; j < 16; j++)
                a += xr[j] * e[lane + 32 * j];
            #pragma unroll
            for (int o = 16; o > 0; o >>= 1)
                a += __shfl_xor_sync(0xffffffffu, a, o);
            float sc = 2.f * a - g_e2[k];
            if (sc > best || (sc == best && k < bi)) { best = sc; bi = k; }
        }
        int approx = g_ind[m];
        if (bi != approx) {                          // uniform across warp
            if (lane == 0) out_ind_f[m] = (float)bi;
            const float* e = embed + (size_t)bi * D_DIM;
            float* oq = out_q + (size_t)b * D_DIM * N_DIM + n;
            #pragma unroll
            for (int j = 0; j < 16; j++)
                oq[(size_t)(lane + 32 * j) * N_DIM] = e[lane + 32 * j];
        }
    }
}

// -------- full fallback: exact scan of all codewords, patch on change -------
__global__ __launch_bounds__(256) void full_kernel(const float* __restrict__ x,
                                                   const float* __restrict__ embed,
                                                   float* __restrict__ out_q,
                                                   float* __restrict__ out_ind_f) {
    __shared__ float xr[D_DIM];
    __shared__ float bv[256];
    __shared__ int   bI[256];
    int nf = g_nfull;
    for (int f = blockIdx.x; f < nf; f += gridDim.x) {
        int m = g_fullm[f];
        int b = m >> 13, n = m & (N_DIM - 1);
        __syncthreads();
        for (int d = threadIdx.x; d < D_DIM; d += 256)
            xr[d] = x[(size_t)b * D_DIM * N_DIM + (size_t)d * N_DIM + n];
        __syncthreads();
        float best = -3.0e38f; int bi = 0x7fffffff;
        for (int c = 0; c < 8; c++) {
            int k = threadIdx.x + c * 256;
            const float4* er = (const float4*)(embed + (size_t)k * D_DIM);
            float s0 = 0.f, s1 = 0.f, s2 = 0.f, s3 = 0.f;
            #pragma unroll 8
            for (int j = 0; j < 128; j++) {
                float4 e = er[j];
                s0 += xr[4 * j + 0] * e.x;
                s1 += xr[4 * j + 1] * e.y;
                s2 += xr[4 * j + 2] * e.z;
                s3 += xr[4 * j + 3] * e.w;
            }
            float sc = 2.f * ((s0 + s1) + (s2 + s3)) - g_e2[k];
            if (sc > best || (sc == best && k < bi)) { best = sc; bi = k; }
        }
        bv[threadIdx.x] = best; bI[threadIdx.x] = bi;
        __syncthreads();
        for (int o = 128; o > 0; o >>= 1) {
            if (threadIdx.x < o) {
                float ov = bv[threadIdx.x + o]; int oi = bI[threadIdx.x + o];
                if (ov > bv[threadIdx.x] || (ov == bv[threadIdx.x] && oi < bI[threadIdx.x])) {
                    bv[threadIdx.x] = ov; bI[threadIdx.x] = oi;
                }
            }
            __syncthreads();
        }
        int fbi = bI[0];
        if (fbi != g_ind[m]) {
            if (threadIdx.x == 0) out_ind_f[m] = (float)fbi;
            const float* e = embed + (size_t)fbi * D_DIM;
            float* oq = out_q + (size_t)b * D_DIM * N_DIM + n;
            for (int d = threadIdx.x; d < D_DIM; d += 256)
                oq[(size_t)d * N_DIM] = e[d];
        }
        __syncthreads();
    }
}

// ---------------------------------------------------------------------------
extern "C" void kernel_launch(void* const* d_in, const int* in_sizes, int n_in,
                              void* d_out, int out_size) {
    const float* x     = (const float*)d_in[0];
    const float* embed = (const float*)d_in[1];
    float* out   = (float*)d_out;
    float* out_q = out;
    float* out_i = out + (size_t)B_DIM * D_DIM * N_DIM;
    (void)in_sizes; (void)n_in; (void)out_size;

    cudaFuncSetAttribute(vq_dist_kernel, cudaFuncAttributeMaxDynamicSharedMemorySize, SM_DIST);

    prep_embed_kernel<<<K_CB, 128>>>(embed);
    prep_x_kernel<<<dim3(N_DIM / 64, B_DIM), 256>>>(x);
    vq_dist_kernel<<<M_ROWS / 128, 256, SM_DIST>>>(embed, out_q, out_i);
    light_kernel<<<1024, 256>>>(x, embed, out_q, out_i);
    full_kernel<<<256, 256>>>(x, embed, out_q, out_i);
}

// round 15
// speedup vs baseline: 5.2815x; 1.0402x over previous
#include <cuda_runtime.h>
#include <cuda_bf16.h>
#include <cstdint>
#include <cstddef>

#define K_CB   2048
#define D_DIM  512
#define B_DIM  16
#define N_DIM  8192
#define M_ROWS (B_DIM * N_DIM)
#define MARGIN 1.0f

// -------- device scratch: hi bf16 plane only, packed in dim-pairs -----------
__device__ uint32_t g_Ah[(size_t)M_ROWS * 256];
__device__ uint32_t g_Bh[(size_t)K_CB * 256];
__device__ float    g_e2[K_CB];
__device__ int      g_ind[M_ROWS];
__device__ int      g_lightm[M_ROWS];
__device__ int      g_cand[(size_t)M_ROWS * 4];
__device__ int      g_fullm[M_ROWS];
__device__ int      g_nlight;
__device__ int      g_nfull;

// -------- helpers --------
__device__ __forceinline__ uint32_t smem_u32(const void* p) {
    uint32_t a;
    asm("{ .reg .u64 t; cvta.to.shared.u64 t, %1; cvt.u32.u64 %0, t; }" : "=r"(a) : "l"(p));
    return a;
}
#define CP_A16(s, g) \
    asm volatile("cp.async.cg.shared.global [%0], [%1], 16;" :: "r"(s), "l"(g) : "memory")
#define CP_COMMIT() asm volatile("cp.async.commit_group;" ::: "memory")
#define CP_WAIT(n)  asm volatile("cp.async.wait_group %0;" :: "n"(n) : "memory")

__device__ __forceinline__ void ldsm4(uint32_t* r, uint32_t addr) {
    asm volatile("ldmatrix.sync.aligned.m8n8.x4.shared.b16 {%0,%1,%2,%3}, [%4];"
                 : "=r"(r[0]), "=r"(r[1]), "=r"(r[2]), "=r"(r[3]) : "r"(addr));
}
__device__ __forceinline__ void mma16816(float* c, const uint32_t* a, const uint32_t* b) {
    asm volatile("mma.sync.aligned.m16n8k16.row.col.f32.bf16.bf16.f32 "
                 "{%0,%1,%2,%3}, {%4,%5,%6,%7}, {%8,%9}, {%0,%1,%2,%3};"
                 : "+f"(c[0]), "+f"(c[1]), "+f"(c[2]), "+f"(c[3])
                 : "r"(a[0]), "r"(a[1]), "r"(a[2]), "r"(a[3]), "r"(b[0]), "r"(b[1]));
}
__device__ __forceinline__ uint32_t bf16hi(float v) {
    return (uint32_t)__bfloat16_as_ushort(__float2bfloat16(v));
}

// -------- prep: codebook hi plane + e2 --------
__global__ __launch_bounds__(128) void prep_embed_kernel(const float* __restrict__ embed) {
    int k = blockIdx.x;
    const float* row = embed + (size_t)k * D_DIM;
    uint32_t* bh = g_Bh + (size_t)k * 256;
    float s = 0.f;
    for (int j = threadIdx.x; j < 256; j += 128) {
        float v0 = row[2 * j], v1 = row[2 * j + 1];
        s += v0 * v0 + v1 * v1;
        bh[j] = bf16hi(v0) | (bf16hi(v1) << 16);
    }
    #pragma unroll
    for (int o = 16; o > 0; o >>= 1) s += __shfl_down_sync(0xffffffffu, s, o);
    __shared__ float ws[4];
    if ((threadIdx.x & 31) == 0) ws[threadIdx.x >> 5] = s;
    __syncthreads();
    if (threadIdx.x == 0) g_e2[k] = ws[0] + ws[1] + ws[2] + ws[3];
    if (blockIdx.x == 0 && threadIdx.x == 0) { g_nlight = 0; g_nfull = 0; }
}

// -------- prep: x[B,D,N] -> row-major hi plane (transpose through smem) -----
__global__ __launch_bounds__(256) void prep_x_kernel(const float* __restrict__ x) {
    __shared__ uint16_t t[64][66];
    int b = blockIdx.y, n0 = blockIdx.x * 64;
    const float* xb = x + (size_t)b * D_DIM * N_DIM + n0;
    for (int dc = 0; dc < 8; dc++) {
        __syncthreads();
        #pragma unroll
        for (int l = 0; l < 16; l++) {
            int i = threadIdx.x + l * 256;
            int dd = i >> 6, nn = i & 63;
            t[dd][nn] = (uint16_t)bf16hi(xb[(size_t)(dc * 64 + dd) * N_DIM + nn]);
        }
        __syncthreads();
        #pragma unroll
        for (int l = 0; l < 8; l++) {
            int i = threadIdx.x + l * 256;
            int nn = i >> 5, jj = i & 31;
            uint32_t p = (uint32_t)t[2 * jj][nn] | ((uint32_t)t[2 * jj + 1][nn] << 16);
            g_Ah[(size_t)(b * N_DIM + n0 + nn) * 256 + dc * 32 + jj] = p;
        }
    }
}

// -------- smem: 2-stage ring, stage = A chunk (16KB) + B chunk (16KB) -------
#define STAGE_BYTES 32768
#define SM_DIST (2 * STAGE_BYTES)

__device__ __forceinline__ void load_tiles(uint32_t ss, const uint4* Ah,
                                           const uint4* Bh, int kb, int tid) {
    #pragma unroll
    for (int l = 0; l < 4; l++) {
        int i = tid + l * 256;
        int row = i >> 3, ch = i & 7;
        uint32_t soff = (uint32_t)row * 128 + (uint32_t)((ch ^ (row & 7)) << 4);
        size_t goff = (size_t)row * 64 + (size_t)kb * 8 + ch;
        CP_A16(ss + soff,         Ah + goff);
        CP_A16(ss + 16384 + soff, Bh + goff);
    }
}

// -------- warp-tile compute: 32x64 per warp, 64 dims/stage, hi x hi ---------
__device__ __forceinline__ void compute_stage(uint32_t ss, int lane, int wm, int wn,
                                              float acc[2][8][4]) {
    uint32_t sAh = ss, sBh = ss + 16384;
    #pragma unroll
    for (int kk = 0; kk < 4; kk++) {
        uint32_t ah[2][4];
        #pragma unroll
        for (int i = 0; i < 2; i++) {
            int r = wm * 32 + i * 16 + (lane & 15);
            int c = (kk * 2 + (lane >> 4)) ^ (r & 7);
            ldsm4(ah[i], sAh + r * 128 + c * 16);
        }
        #pragma unroll
        for (int j16 = 0; j16 < 4; j16++) {
            int n = wn * 64 + j16 * 16 + (lane & 7) + ((lane >> 4) << 3);
            int c = (kk * 2 + ((lane >> 3) & 1)) ^ (n & 7);
            uint32_t bh[4];
            ldsm4(bh, sBh + n * 128 + c * 16);
            #pragma unroll
            for (int i = 0; i < 2; i++) {
                mma16816(acc[i][j16 * 2 + 0], ah[i], bh + 0);
                mma16816(acc[i][j16 * 2 + 1], ah[i], bh + 2);
            }
        }
    }
}

#define INS3(r, s, k) do {                                                        \
    if ((s) > v1[r]) { v3[r] = v2[r]; v2[r] = v1[r]; i2[r] = i1[r];               \
                       v1[r] = (s); i1[r] = (k); }                                \
    else if ((s) > v2[r]) { v3[r] = v2[r]; v2[r] = (s); i2[r] = (k); }            \
    else if ((s) > v3[r]) { v3[r] = (s); }                                        \
} while (0)

// -------- main dist + argmax/classify kernel --------
__global__ void __launch_bounds__(256, 2) vq_dist_kernel(float* __restrict__ out_ind_f) {
    extern __shared__ char smem[];
    uint32_t sb = smem_u32(smem);
    const int tid = threadIdx.x, lane = tid & 31, wid = tid >> 5;
    const int wm = wid & 3, wn = wid >> 2;
    const int m0 = blockIdx.x * 128;
    const uint4* Ah = (const uint4*)(g_Ah + (size_t)m0 * 256);

    float v1[4], v2[4], v3[4];
    int   i1[4], i2[4];
    #pragma unroll
    for (int r = 0; r < 4; r++) {
        v1[r] = v2[r] = v3[r] = -3.0e38f;
        i1[r] = i2[r] = 0;
    }

    for (int nt = 0; nt < 16; nt++) {
        const uint4* Bh = (const uint4*)(g_Bh + (size_t)nt * 128 * 256);

        float acc[2][8][4];
        #pragma unroll
        for (int i = 0; i < 2; i++)
            #pragma unroll
            for (int j = 0; j < 8; j++)
                #pragma unroll
                for (int q = 0; q < 4; q++) acc[i][j][q] = 0.f;

        load_tiles(sb, Ah, Bh, 0, tid);
        CP_COMMIT();
        for (int kb = 0; kb < 8; kb++) {
            uint32_t cur = sb + (kb & 1) * STAGE_BYTES;
            if (kb < 7) {
                load_tiles(sb + ((kb + 1) & 1) * STAGE_BYTES, Ah, Bh, kb + 1, tid);
                CP_COMMIT();
                CP_WAIT(1);
            } else {
                CP_WAIT(0);
            }
            __syncthreads();
            compute_stage(cur, lane, wm, wn, acc);
            __syncthreads();
        }

        #pragma unroll
        for (int j = 0; j < 8; j++) {
            int kb_ = nt * 128 + wn * 64 + j * 8 + (lane & 3) * 2;
            float e2a = g_e2[kb_], e2b = g_e2[kb_ + 1];
            #pragma unroll
            for (int i = 0; i < 2; i++) {
                float s0 = 2.f * acc[i][j][0] - e2a;
                float s1 = 2.f * acc[i][j][1] - e2b;
                float s2 = 2.f * acc[i][j][2] - e2a;
                float s3 = 2.f * acc[i][j][3] - e2b;
                int r0 = i * 2, r1 = i * 2 + 1;
                INS3(r0, s0, kb_);
                INS3(r0, s1, kb_ + 1);
                INS3(r1, s2, kb_);
                INS3(r1, s3, kb_ + 1);
            }
        }
    }

    // ---- per-row merge over 8 sources, classify row ----
    float* sV = (float*)smem;                   // [128][8][3]
    int*   sI = (int*)(smem + 128 * 8 * 3 * 4); // [128][8][2]
    __syncthreads();
    #pragma unroll
    for (int r = 0; r < 4; r++) {
        int row = wm * 32 + (r >> 1) * 16 + (r & 1) * 8 + (lane >> 2);
        int src = wn * 4 + (lane & 3);
        float* v = sV + (row * 8 + src) * 3;
        v[0] = v1[r]; v[1] = v2[r]; v[2] = v3[r];
        int* ii = sI + (row * 8 + src) * 2;
        ii[0] = i1[r]; ii[1] = i2[r];
    }
    __syncthreads();
    if (tid < 128) {
        float b1 = -3.0e38f; int bi1 = 0x7fffffff;
        #pragma unroll
        for (int s = 0; s < 8; s++) {
            float v = sV[(tid * 8 + s) * 3];
            int   i = sI[(tid * 8 + s) * 2];
            if (v > b1 || (v == b1 && i < bi1)) { b1 = v; bi1 = i; }
        }
        float thr = b1 - MARGIN;
        int cand[4]; int nc = 0; bool overflow = false;
        #pragma unroll
        for (int s = 0; s < 8; s++) {
            float va = sV[(tid * 8 + s) * 3 + 0];
            float vb = sV[(tid * 8 + s) * 3 + 1];
            float vc = sV[(tid * 8 + s) * 3 + 2];
            int ia = sI[(tid * 8 + s) * 2 + 0];
            int ib = sI[(tid * 8 + s) * 2 + 1];
            if (va >= thr) { if (nc < 4) cand[nc] = ia; nc++; }
            if (vb >= thr) { if (nc < 4) cand[nc] = ib; nc++; }
            if (vc >= thr) overflow = true;
        }
        int m = m0 + tid;
        g_ind[m] = bi1;
        out_ind_f[m] = (float)bi1;
        if (!overflow && nc > 1 && nc <= 4) {
            int slot = atomicAdd(&g_nlight, 1);
            g_lightm[slot] = m;
            #pragma unroll
            for (int c = 0; c < 4; c++) g_cand[(size_t)slot * 4 + c] = (c < nc) ? cand[c] : -1;
        } else if (overflow || nc > 4) {
            int slot = atomicAdd(&g_nfull, 1);
            g_fullm[slot] = m;
        }
    }
}

// -------- light fallback: exact rescore of <=4 candidates, WARP per row -----
__global__ __launch_bounds__(256) void light_kernel(const float* __restrict__ x,
                                                    const float* __restrict__ embed,
                                                    float* __restrict__ out_ind_f) {
    const int nl = g_nlight;
    const int lane = threadIdx.x & 31;
    const int wglob = blockIdx.x * 8 + (threadIdx.x >> 5);
    for (int s = wglob; s < nl; s += gridDim.x * 8) {
        int m = g_lightm[s];
        int b = m >> 13, n = m & (N_DIM - 1);
        const float* xb = x + (size_t)b * D_DIM * N_DIM + n;
        float xr[16];
        #pragma unroll
        for (int j = 0; j < 16; j++)
            xr[j] = xb[(size_t)(lane + 32 * j) * N_DIM];
        float best = -3.0e38f; int bi = 0x7fffffff;
        #pragma unroll
        for (int c = 0; c < 4; c++) {
            int k = g_cand[(size_t)s * 4 + c];
            if (k < 0) break;
            const float* e = embed + (size_t)k * D_DIM;
            float a = 0.f;
            #pragma unroll
            for (int j = 0; j < 16; j++)
                a += xr[j] * e[lane + 32 * j];
            #pragma unroll
            for (int o = 16; o > 0; o >>= 1)
                a += __shfl_xor_sync(0xffffffffu, a, o);
            float sc = 2.f * a - g_e2[k];
            if (sc > best || (sc == best && k < bi)) { best = sc; bi = k; }
        }
        if (lane == 0) { g_ind[m] = bi; out_ind_f[m] = (float)bi; }
    }
}

// -------- full fallback: exact scan of all codewords (rare) --------
__global__ __launch_bounds__(256) void full_kernel(const float* __restrict__ x,
                                                   const float* __restrict__ embed,
                                                   float* __restrict__ out_ind_f) {
    __shared__ float xr[D_DIM];
    __shared__ float bv[256];
    __shared__ int   bI[256];
    int nf = g_nfull;
    for (int f = blockIdx.x; f < nf; f += gridDim.x) {
        int m = g_fullm[f];
        int b = m >> 13, n = m & (N_DIM - 1);
        __syncthreads();
        for (int d = threadIdx.x; d < D_DIM; d += 256)
            xr[d] = x[(size_t)b * D_DIM * N_DIM + (size_t)d * N_DIM + n];
        __syncthreads();
        float best = -3.0e38f; int bi = 0x7fffffff;
        for (int c = 0; c < 8; c++) {
            int k = threadIdx.x + c * 256;
            const float4* er = (const float4*)(embed + (size_t)k * D_DIM);
            float s0 = 0.f, s1 = 0.f, s2 = 0.f, s3 = 0.f;
            #pragma unroll 8
            for (int j = 0; j < 128; j++) {
                float4 e = er[j];
                s0 += xr[4 * j + 0] * e.x;
                s1 += xr[4 * j + 1] * e.y;
                s2 += xr[4 * j + 2] * e.z;
                s3 += xr[4 * j + 3] * e.w;
            }
            float sc = 2.f * ((s0 + s1) + (s2 + s3)) - g_e2[k];
            if (sc > best || (sc == best && k < bi)) { best = sc; bi = k; }
        }
        bv[threadIdx.x] = best; bI[threadIdx.x] = bi;
        __syncthreads();
        for (int o = 128; o > 0; o >>= 1) {
            if (threadIdx.x < o) {
                float ov = bv[threadIdx.x + o]; int oi = bI[threadIdx.x + o];
                if (ov > bv[threadIdx.x] || (ov == bv[threadIdx.x] && oi < bI[threadIdx.x])) {
                    bv[threadIdx.x] = ov; bI[threadIdx.x] = oi;
                }
            }
            __syncthreads();
        }
        if (threadIdx.x == 0) { g_ind[m] = bI[0]; out_ind_f[m] = (float)bI[0]; }
        __syncthreads();
    }
}

// -------- gather v2: out[b,d,n] = embed[ind[b,n], d] --------
// phase1: LDG.128 (coalesced) -> STS.128 with 16B-unit XOR swizzle
// phase2: swizzled LDS -> n-fast coalesced 128B global writes
__global__ __launch_bounds__(512) void gather_kernel(const float* __restrict__ embed,
                                                     float* __restrict__ out) {
    __shared__ float4 tile[32 * 128];   // 64 KB
    __shared__ int inds[32];
    const int tid = threadIdx.x;
    const int bb = blockIdx.y;
    const int n0 = blockIdx.x * 32;
    if (tid < 32) inds[tid] = g_ind[bb * N_DIM + n0 + tid];
    __syncthreads();
    #pragma unroll
    for (int l = 0; l < 8; l++) {
        int i = tid + l * 512;
        int n = i >> 7, d4 = i & 127;
        float4 v = ((const float4*)(embed + (size_t)inds[n] * D_DIM))[d4];
        tile[n * 128 + (d4 ^ (n & 7))] = v;
    }
    __syncthreads();
    float* obase = out + (size_t)bb * D_DIM * N_DIM + n0;
    const float* tw = (const float*)tile;
    #pragma unroll
    for (int l = 0; l < 32; l++) {
        int i = tid + l * 512;
        int n = i & 31, d = i >> 5;
        int u = (d >> 2) ^ (n & 7);
        obase[(size_t)d * N_DIM + n] = tw[n * 512 + u * 4 + (d & 3)];
    }
}

// ---------------------------------------------------------------------------
extern "C" void kernel_launch(void* const* d_in, const int* in_sizes, int n_in,
                              void* d_out, int out_size) {
    const float* x     = (const float*)d_in[0];
    const float* embed = (const float*)d_in[1];
    float* out   = (float*)d_out;
    float* out_q = out;
    float* out_i = out + (size_t)B_DIM * D_DIM * N_DIM;
    (void)in_sizes; (void)n_in; (void)out_size;

    cudaFuncSetAttribute(vq_dist_kernel, cudaFuncAttributeMaxDynamicSharedMemorySize, SM_DIST);

    prep_embed_kernel<<<K_CB, 128>>>(embed);
    prep_x_kernel<<<dim3(N_DIM / 64, B_DIM), 256>>>(x);
    vq_dist_kernel<<<M_ROWS / 128, 256, SM_DIST>>>(out_i);
    light_kernel<<<1024, 256>>>(x, embed, out_i);
    full_kernel<<<256, 256>>>(x, embed, out_i);
    gather_kernel<<<dim3(N_DIM / 32, B_DIM), 512>>>(embed, out_q);
}

// round 16
// speedup vs baseline: 5.6546x; 1.0707x over previous
#include <cuda_runtime.h>
#include <cuda_bf16.h>
#include <cstdint>
#include <cstddef>

#define K_CB   2048
#define D_DIM  512
#define B_DIM  16
#define N_DIM  8192
#define M_ROWS (B_DIM * N_DIM)
#define MARGIN 1.0f

// -------- device scratch: hi bf16 plane only, packed in dim-pairs -----------
__device__ uint32_t g_Ah[(size_t)M_ROWS * 256];
__device__ uint32_t g_Bh[(size_t)K_CB * 256];
__device__ float    g_e2[K_CB];
__device__ int      g_ind[M_ROWS];
__device__ int      g_lightm[M_ROWS];
__device__ int      g_cand[(size_t)M_ROWS * 4];
__device__ int      g_fullm[M_ROWS];
__device__ int      g_nlight;
__device__ int      g_nfull;

// -------- helpers --------
__device__ __forceinline__ uint32_t smem_u32(const void* p) {
    uint32_t a;
    asm("{ .reg .u64 t; cvta.to.shared.u64 t, %1; cvt.u32.u64 %0, t; }" : "=r"(a) : "l"(p));
    return a;
}
#define CP_A16(s, g) \
    asm volatile("cp.async.cg.shared.global [%0], [%1], 16;" :: "r"(s), "l"(g) : "memory")
#define CP_COMMIT() asm volatile("cp.async.commit_group;" ::: "memory")
#define CP_WAIT(n)  asm volatile("cp.async.wait_group %0;" :: "n"(n) : "memory")

__device__ __forceinline__ void ldsm4(uint32_t* r, uint32_t addr) {
    asm volatile("ldmatrix.sync.aligned.m8n8.x4.shared.b16 {%0,%1,%2,%3}, [%4];"
                 : "=r"(r[0]), "=r"(r[1]), "=r"(r[2]), "=r"(r[3]) : "r"(addr));
}
__device__ __forceinline__ void mma16816(float* c, const uint32_t* a, const uint32_t* b) {
    asm volatile("mma.sync.aligned.m16n8k16.row.col.f32.bf16.bf16.f32 "
                 "{%0,%1,%2,%3}, {%4,%5,%6,%7}, {%8,%9}, {%0,%1,%2,%3};"
                 : "+f"(c[0]), "+f"(c[1]), "+f"(c[2]), "+f"(c[3])
                 : "r"(a[0]), "r"(a[1]), "r"(a[2]), "r"(a[3]), "r"(b[0]), "r"(b[1]));
}
__device__ __forceinline__ uint32_t bf16hi(float v) {
    return (uint32_t)__bfloat16_as_ushort(__float2bfloat16(v));
}
// pack two floats -> (bf16(lo) | bf16(hi)<<16) in one instruction
__device__ __forceinline__ uint32_t bf16x2(float lo, float hi) {
    uint32_t r;
    asm("cvt.rn.bf16x2.f32 %0, %1, %2;" : "=r"(r) : "f"(hi), "f"(lo));
    return r;
}

// -------- prep: codebook hi plane + e2 --------
__global__ __launch_bounds__(128) void prep_embed_kernel(const float* __restrict__ embed) {
    int k = blockIdx.x;
    const float* row = embed + (size_t)k * D_DIM;
    uint32_t* bh = g_Bh + (size_t)k * 256;
    float s = 0.f;
    for (int j = threadIdx.x; j < 256; j += 128) {
        float v0 = row[2 * j], v1 = row[2 * j + 1];
        s += v0 * v0 + v1 * v1;
        bh[j] = bf16hi(v0) | (bf16hi(v1) << 16);
    }
    #pragma unroll
    for (int o = 16; o > 0; o >>= 1) s += __shfl_down_sync(0xffffffffu, s, o);
    __shared__ float ws[4];
    if ((threadIdx.x & 31) == 0) ws[threadIdx.x >> 5] = s;
    __syncthreads();
    if (threadIdx.x == 0) g_e2[k] = ws[0] + ws[1] + ws[2] + ws[3];
    if (blockIdx.x == 0 && threadIdx.x == 0) { g_nlight = 0; g_nfull = 0; }
}

// -------- prep v2: x[B,D,N] -> row-major hi plane, float4 loads -------------
__global__ __launch_bounds__(256) void prep_x_kernel(const float* __restrict__ x) {
    __shared__ uint16_t t[64][66];   // [dim][n], 132B row stride
    int b = blockIdx.y, n0 = blockIdx.x * 64;
    const float* xb = x + (size_t)b * D_DIM * N_DIM + n0;
    for (int dc = 0; dc < 8; dc++) {
        __syncthreads();
        // load phase: 1024 float4 = 64 dims x 64 n, fully coalesced
        #pragma unroll
        for (int l = 0; l < 4; l++) {
            int i = threadIdx.x + l * 256;
            int dd = i >> 4, nf = (i & 15) * 4;
            float4 v = *(const float4*)(xb + (size_t)(dc * 64 + dd) * N_DIM + nf);
            uint32_t* tw = (uint32_t*)&t[dd][nf];   // 4B-aligned (nf even)
            tw[0] = bf16x2(v.x, v.y);
            tw[1] = bf16x2(v.z, v.w);
        }
        __syncthreads();
        // write phase: pack dim-pairs, coalesced 128B segments
        #pragma unroll
        for (int l = 0; l < 8; l++) {
            int i = threadIdx.x + l * 256;
            int nn = i >> 5, jj = i & 31;
            uint32_t p = (uint32_t)t[2 * jj][nn] | ((uint32_t)t[2 * jj + 1][nn] << 16);
            g_Ah[(size_t)(b * N_DIM + n0 + nn) * 256 + dc * 32 + jj] = p;
        }
    }
}

// -------- smem: 2-stage ring, stage = A chunk (16KB) + B chunk (16KB) -------
#define STAGE_BYTES 32768
#define SM_DIST (2 * STAGE_BYTES)

__device__ __forceinline__ void load_tiles(uint32_t ss, const uint4* Ah,
                                           const uint4* Bh, int kb, int tid) {
    #pragma unroll
    for (int l = 0; l < 4; l++) {
        int i = tid + l * 256;
        int row = i >> 3, ch = i & 7;
        uint32_t soff = (uint32_t)row * 128 + (uint32_t)((ch ^ (row & 7)) << 4);
        size_t goff = (size_t)row * 64 + (size_t)kb * 8 + ch;
        CP_A16(ss + soff,         Ah + goff);
        CP_A16(ss + 16384 + soff, Bh + goff);
    }
}

// -------- warp-tile compute: 32x64 per warp, 64 dims/stage, hi x hi ---------
__device__ __forceinline__ void compute_stage(uint32_t ss, int lane, int wm, int wn,
                                              float acc[2][8][4]) {
    uint32_t sAh = ss, sBh = ss + 16384;
    #pragma unroll
    for (int kk = 0; kk < 4; kk++) {
        uint32_t ah[2][4];
        #pragma unroll
        for (int i = 0; i < 2; i++) {
            int r = wm * 32 + i * 16 + (lane & 15);
            int c = (kk * 2 + (lane >> 4)) ^ (r & 7);
            ldsm4(ah[i], sAh + r * 128 + c * 16);
        }
        #pragma unroll
        for (int j16 = 0; j16 < 4; j16++) {
            int n = wn * 64 + j16 * 16 + (lane & 7) + ((lane >> 4) << 3);
            int c = (kk * 2 + ((lane >> 3) & 1)) ^ (n & 7);
            uint32_t bh[4];
            ldsm4(bh, sBh + n * 128 + c * 16);
            #pragma unroll
            for (int i = 0; i < 2; i++) {
                mma16816(acc[i][j16 * 2 + 0], ah[i], bh + 0);
                mma16816(acc[i][j16 * 2 + 1], ah[i], bh + 2);
            }
        }
    }
}

#define INS3(r, s, k) do {                                                        \
    if ((s) > v1[r]) { v3[r] = v2[r]; v2[r] = v1[r]; i2[r] = i1[r];               \
                       v1[r] = (s); i1[r] = (k); }                                \
    else if ((s) > v2[r]) { v3[r] = v2[r]; v2[r] = (s); i2[r] = (k); }            \
    else if ((s) > v3[r]) { v3[r] = (s); }                                        \
} while (0)

// -------- main dist + argmax/classify kernel --------
__global__ void __launch_bounds__(256, 2) vq_dist_kernel(float* __restrict__ out_ind_f) {
    extern __shared__ char smem[];
    uint32_t sb = smem_u32(smem);
    const int tid = threadIdx.x, lane = tid & 31, wid = tid >> 5;
    const int wm = wid & 3, wn = wid >> 2;
    const int m0 = blockIdx.x * 128;
    const uint4* Ah = (const uint4*)(g_Ah + (size_t)m0 * 256);

    float v1[4], v2[4], v3[4];
    int   i1[4], i2[4];
    #pragma unroll
    for (int r = 0; r < 4; r++) {
        v1[r] = v2[r] = v3[r] = -3.0e38f;
        i1[r] = i2[r] = 0;
    }

    for (int nt = 0; nt < 16; nt++) {
        const uint4* Bh = (const uint4*)(g_Bh + (size_t)nt * 128 * 256);

        float acc[2][8][4];
        #pragma unroll
        for (int i = 0; i < 2; i++)
            #pragma unroll
            for (int j = 0; j < 8; j++)
                #pragma unroll
                for (int q = 0; q < 4; q++) acc[i][j][q] = 0.f;

        load_tiles(sb, Ah, Bh, 0, tid);
        CP_COMMIT();
        for (int kb = 0; kb < 8; kb++) {
            uint32_t cur = sb + (kb & 1) * STAGE_BYTES;
            if (kb < 7) {
                load_tiles(sb + ((kb + 1) & 1) * STAGE_BYTES, Ah, Bh, kb + 1, tid);
                CP_COMMIT();
                CP_WAIT(1);
            } else {
                CP_WAIT(0);
            }
            __syncthreads();
            compute_stage(cur, lane, wm, wn, acc);
            __syncthreads();
        }

        #pragma unroll
        for (int j = 0; j < 8; j++) {
            int kb_ = nt * 128 + wn * 64 + j * 8 + (lane & 3) * 2;
            float e2a = g_e2[kb_], e2b = g_e2[kb_ + 1];
            #pragma unroll
            for (int i = 0; i < 2; i++) {
                float s0 = 2.f * acc[i][j][0] - e2a;
                float s1 = 2.f * acc[i][j][1] - e2b;
                float s2 = 2.f * acc[i][j][2] - e2a;
                float s3 = 2.f * acc[i][j][3] - e2b;
                int r0 = i * 2, r1 = i * 2 + 1;
                INS3(r0, s0, kb_);
                INS3(r0, s1, kb_ + 1);
                INS3(r1, s2, kb_);
                INS3(r1, s3, kb_ + 1);
            }
        }
    }

    // ---- per-row merge over 8 sources, classify row ----
    float* sV = (float*)smem;                   // [128][8][3]
    int*   sI = (int*)(smem + 128 * 8 * 3 * 4); // [128][8][2]
    __syncthreads();
    #pragma unroll
    for (int r = 0; r < 4; r++) {
        int row = wm * 32 + (r >> 1) * 16 + (r & 1) * 8 + (lane >> 2);
        int src = wn * 4 + (lane & 3);
        float* v = sV + (row * 8 + src) * 3;
        v[0] = v1[r]; v[1] = v2[r]; v[2] = v3[r];
        int* ii = sI + (row * 8 + src) * 2;
        ii[0] = i1[r]; ii[1] = i2[r];
    }
    __syncthreads();
    if (tid < 128) {
        float b1 = -3.0e38f; int bi1 = 0x7fffffff;
        #pragma unroll
        for (int s = 0; s < 8; s++) {
            float v = sV[(tid * 8 + s) * 3];
            int   i = sI[(tid * 8 + s) * 2];
            if (v > b1 || (v == b1 && i < bi1)) { b1 = v; bi1 = i; }
        }
        float thr = b1 - MARGIN;
        int cand[4]; int nc = 0; bool overflow = false;
        #pragma unroll
        for (int s = 0; s < 8; s++) {
            float va = sV[(tid * 8 + s) * 3 + 0];
            float vb = sV[(tid * 8 + s) * 3 + 1];
            float vc = sV[(tid * 8 + s) * 3 + 2];
            int ia = sI[(tid * 8 + s) * 2 + 0];
            int ib = sI[(tid * 8 + s) * 2 + 1];
            if (va >= thr) { if (nc < 4) cand[nc] = ia; nc++; }
            if (vb >= thr) { if (nc < 4) cand[nc] = ib; nc++; }
            if (vc >= thr) overflow = true;
        }
        int m = m0 + tid;
        g_ind[m] = bi1;
        out_ind_f[m] = (float)bi1;
        if (!overflow && nc > 1 && nc <= 4) {
            int slot = atomicAdd(&g_nlight, 1);
            g_lightm[slot] = m;
            #pragma unroll
            for (int c = 0; c < 4; c++) g_cand[(size_t)slot * 4 + c] = (c < nc) ? cand[c] : -1;
        } else if (overflow || nc > 4) {
            int slot = atomicAdd(&g_nfull, 1);
            g_fullm[slot] = m;
        }
    }
}

// -------- light fallback: exact rescore of <=4 candidates, WARP per row -----
__global__ __launch_bounds__(256) void light_kernel(const float* __restrict__ x,
                                                    const float* __restrict__ embed,
                                                    float* __restrict__ out_ind_f) {
    const int nl = g_nlight;
    const int lane = threadIdx.x & 31;
    const int wglob = blockIdx.x * 8 + (threadIdx.x >> 5);
    for (int s = wglob; s < nl; s += gridDim.x * 8) {
        int m = g_lightm[s];
        int b = m >> 13, n = m & (N_DIM - 1);
        const float* xb = x + (size_t)b * D_DIM * N_DIM + n;
        float xr[16];
        #pragma unroll
        for (int j = 0; j < 16; j++)
            xr[j] = xb[(size_t)(lane + 32 * j) * N_DIM];
        float best = -3.0e38f; int bi = 0x7fffffff;
        #pragma unroll
        for (int c = 0; c < 4; c++) {
            int k = g_cand[(size_t)s * 4 + c];
            if (k < 0) break;
            const float* e = embed + (size_t)k * D_DIM;
            float a = 0.f;
            #pragma unroll
            for (int j = 0; j < 16; j++)
                a += xr[j] * e[lane + 32 * j];
            #pragma unroll
            for (int o = 16; o > 0; o >>= 1)
                a += __shfl_xor_sync(0xffffffffu, a, o);
            float sc = 2.f * a - g_e2[k];
            if (sc > best || (sc == best && k < bi)) { best = sc; bi = k; }
        }
        if (lane == 0) { g_ind[m] = bi; out_ind_f[m] = (float)bi; }
    }
}

// -------- full fallback: exact scan of all codewords (rare) --------
__global__ __launch_bounds__(256) void full_kernel(const float* __restrict__ x,
                                                   const float* __restrict__ embed,
                                                   float* __restrict__ out_ind_f) {
    __shared__ float xr[D_DIM];
    __shared__ float bv[256];
    __shared__ int   bI[256];
    int nf = g_nfull;
    for (int f = blockIdx.x; f < nf; f += gridDim.x) {
        int m = g_fullm[f];
        int b = m >> 13, n = m & (N_DIM - 1);
        __syncthreads();
        for (int d = threadIdx.x; d < D_DIM; d += 256)
            xr[d] = x[(size_t)b * D_DIM * N_DIM + (size_t)d * N_DIM + n];
        __syncthreads();
        float best = -3.0e38f; int bi = 0x7fffffff;
        for (int c = 0; c < 8; c++) {
            int k = threadIdx.x + c * 256;
            const float4* er = (const float4*)(embed + (size_t)k * D_DIM);
            float s0 = 0.f, s1 = 0.f, s2 = 0.f, s3 = 0.f;
            #pragma unroll 8
            for (int j = 0; j < 128; j++) {
                float4 e = er[j];
                s0 += xr[4 * j + 0] * e.x;
                s1 += xr[4 * j + 1] * e.y;
                s2 += xr[4 * j + 2] * e.z;
                s3 += xr[4 * j + 3] * e.w;
            }
            float sc = 2.f * ((s0 + s1) + (s2 + s3)) - g_e2[k];
            if (sc > best || (sc == best && k < bi)) { best = sc; bi = k; }
        }
        bv[threadIdx.x] = best; bI[threadIdx.x] = bi;
        __syncthreads();
        for (int o = 128; o > 0; o >>= 1) {
            if (threadIdx.x < o) {
                float ov = bv[threadIdx.x + o]; int oi = bI[threadIdx.x + o];
                if (ov > bv[threadIdx.x] || (ov == bv[threadIdx.x] && oi < bI[threadIdx.x])) {
                    bv[threadIdx.x] = ov; bI[threadIdx.x] = oi;
                }
            }
            __syncthreads();
        }
        if (threadIdx.x == 0) { g_ind[m] = bI[0]; out_ind_f[m] = (float)bI[0]; }
        __syncthreads();
    }
}

// -------- gather v2: out[b,d,n] = embed[ind[b,n], d] --------
__global__ __launch_bounds__(512) void gather_kernel(const float* __restrict__ embed,
                                                     float* __restrict__ out) {
    __shared__ float4 tile[32 * 128];   // 64 KB
    __shared__ int inds[32];
    const int tid = threadIdx.x;
    const int bb = blockIdx.y;
    const int n0 = blockIdx.x * 32;
    if (tid < 32) inds[tid] = g_ind[bb * N_DIM + n0 + tid];
    __syncthreads();
    #pragma unroll
    for (int l = 0; l < 8; l++) {
        int i = tid + l * 512;
        int n = i >> 7, d4 = i & 127;
        float4 v = ((const float4*)(embed + (size_t)inds[n] * D_DIM))[d4];
        tile[n * 128 + (d4 ^ (n & 7))] = v;
    }
    __syncthreads();
    float* obase = out + (size_t)bb * D_DIM * N_DIM + n0;
    const float* tw = (const float*)tile;
    #pragma unroll
    for (int l = 0; l < 32; l++) {
        int i = tid + l * 512;
        int n = i & 31, d = i >> 5;
        int u = (d >> 2) ^ (n & 7);
        obase[(size_t)d * N_DIM + n] = tw[n * 512 + u * 4 + (d & 3)];
    }
}

// ---------------------------------------------------------------------------
extern "C" void kernel_launch(void* const* d_in, const int* in_sizes, int n_in,
                              void* d_out, int out_size) {
    const float* x     = (const float*)d_in[0];
    const float* embed = (const float*)d_in[1];
    float* out   = (float*)d_out;
    float* out_q = out;
    float* out_i = out + (size_t)B_DIM * D_DIM * N_DIM;
    (void)in_sizes; (void)n_in; (void)out_size;

    cudaFuncSetAttribute(vq_dist_kernel, cudaFuncAttributeMaxDynamicSharedMemorySize, SM_DIST);

    prep_embed_kernel<<<K_CB, 128>>>(embed);
    prep_x_kernel<<<dim3(N_DIM / 64, B_DIM), 256>>>(x);
    vq_dist_kernel<<<M_ROWS / 128, 256, SM_DIST>>>(out_i);
    light_kernel<<<1024, 256>>>(x, embed, out_i);
    full_kernel<<<256, 256>>>(x, embed, out_i);
    gather_kernel<<<dim3(N_DIM / 32, B_DIM), 512>>>(embed, out_q);
}

// round 17
// speedup vs baseline: 5.7287x; 1.0131x over previous
#include <cuda_runtime.h>
#include <cuda_bf16.h>
#include <cstdint>
#include <cstddef>

#define K_CB   2048
#define D_DIM  512
#define B_DIM  16
#define N_DIM  8192
#define M_ROWS (B_DIM * N_DIM)
#define MARGIN 1.0f

// -------- device scratch: hi bf16 plane only, packed in dim-pairs -----------
__device__ uint32_t g_Ah[(size_t)M_ROWS * 256];
__device__ uint32_t g_Bh[(size_t)K_CB * 256];
__device__ float    g_e2[K_CB];
__device__ int      g_ind[M_ROWS];
__device__ int      g_lightm[M_ROWS];
__device__ int      g_cand[(size_t)M_ROWS * 4];
__device__ int      g_fullm[M_ROWS];
__device__ int      g_nlight;
__device__ int      g_nfull;

// -------- helpers --------
__device__ __forceinline__ uint32_t smem_u32(const void* p) {
    uint32_t a;
    asm("{ .reg .u64 t; cvta.to.shared.u64 t, %1; cvt.u32.u64 %0, t; }" : "=r"(a) : "l"(p));
    return a;
}
#define CP_A16(s, g) \
    asm volatile("cp.async.cg.shared.global [%0], [%1], 16;" :: "r"(s), "l"(g) : "memory")
#define CP_COMMIT() asm volatile("cp.async.commit_group;" ::: "memory")
#define CP_WAIT(n)  asm volatile("cp.async.wait_group %0;" :: "n"(n) : "memory")

__device__ __forceinline__ void ldsm4(uint32_t* r, uint32_t addr) {
    asm volatile("ldmatrix.sync.aligned.m8n8.x4.shared.b16 {%0,%1,%2,%3}, [%4];"
                 : "=r"(r[0]), "=r"(r[1]), "=r"(r[2]), "=r"(r[3]) : "r"(addr));
}
__device__ __forceinline__ void mma16816(float* c, const uint32_t* a, const uint32_t* b) {
    asm volatile("mma.sync.aligned.m16n8k16.row.col.f32.bf16.bf16.f32 "
                 "{%0,%1,%2,%3}, {%4,%5,%6,%7}, {%8,%9}, {%0,%1,%2,%3};"
                 : "+f"(c[0]), "+f"(c[1]), "+f"(c[2]), "+f"(c[3])
                 : "r"(a[0]), "r"(a[1]), "r"(a[2]), "r"(a[3]), "r"(b[0]), "r"(b[1]));
}
__device__ __forceinline__ uint32_t bf16hi(float v) {
    return (uint32_t)__bfloat16_as_ushort(__float2bfloat16(v));
}
__device__ __forceinline__ uint32_t bf16x2(float lo, float hi) {
    uint32_t r;
    asm("cvt.rn.bf16x2.f32 %0, %1, %2;" : "=r"(r) : "f"(hi), "f"(lo));
    return r;
}

// -------- prep: codebook hi plane + e2 --------
__global__ __launch_bounds__(128) void prep_embed_kernel(const float* __restrict__ embed) {
    int k = blockIdx.x;
    const float* row = embed + (size_t)k * D_DIM;
    uint32_t* bh = g_Bh + (size_t)k * 256;
    float s = 0.f;
    for (int j = threadIdx.x; j < 256; j += 128) {
        float v0 = row[2 * j], v1 = row[2 * j + 1];
        s += v0 * v0 + v1 * v1;
        bh[j] = bf16hi(v0) | (bf16hi(v1) << 16);
    }
    #pragma unroll
    for (int o = 16; o > 0; o >>= 1) s += __shfl_down_sync(0xffffffffu, s, o);
    __shared__ float ws[4];
    if ((threadIdx.x & 31) == 0) ws[threadIdx.x >> 5] = s;
    __syncthreads();
    if (threadIdx.x == 0) g_e2[k] = ws[0] + ws[1] + ws[2] + ws[3];
    if (blockIdx.x == 0 && threadIdx.x == 0) { g_nlight = 0; g_nfull = 0; }
}

// -------- prep v2: x[B,D,N] -> row-major hi plane, float4 loads -------------
__global__ __launch_bounds__(256) void prep_x_kernel(const float* __restrict__ x) {
    __shared__ uint16_t t[64][66];
    int b = blockIdx.y, n0 = blockIdx.x * 64;
    const float* xb = x + (size_t)b * D_DIM * N_DIM + n0;
    for (int dc = 0; dc < 8; dc++) {
        __syncthreads();
        #pragma unroll
        for (int l = 0; l < 4; l++) {
            int i = threadIdx.x + l * 256;
            int dd = i >> 4, nf = (i & 15) * 4;
            float4 v = *(const float4*)(xb + (size_t)(dc * 64 + dd) * N_DIM + nf);
            uint32_t* tw = (uint32_t*)&t[dd][nf];
            tw[0] = bf16x2(v.x, v.y);
            tw[1] = bf16x2(v.z, v.w);
        }
        __syncthreads();
        #pragma unroll
        for (int l = 0; l < 8; l++) {
            int i = threadIdx.x + l * 256;
            int nn = i >> 5, jj = i & 31;
            uint32_t p = (uint32_t)t[2 * jj][nn] | ((uint32_t)t[2 * jj + 1][nn] << 16);
            g_Ah[(size_t)(b * N_DIM + n0 + nn) * 256 + dc * 32 + jj] = p;
        }
    }
}

// -------- smem: 3-stage ring, stage = A chunk (16KB) + B chunk (16KB) -------
#define STAGE_BYTES 32768
#define SM_DIST (3 * STAGE_BYTES)   // 96 KB -> still 2 CTAs/SM

// chunk c: nt = c>>3, kb = c&7 (64-dim slice)
__device__ __forceinline__ void load_chunk(uint32_t dst, const uint4* Ah,
                                           const uint4* Bg, int c, int tid) {
    const uint4* Bh = Bg + (size_t)(c >> 3) * 8192;
    int kb = c & 7;
    #pragma unroll
    for (int l = 0; l < 4; l++) {
        int i = tid + l * 256;
        int row = i >> 3, ch = i & 7;
        uint32_t soff = (uint32_t)row * 128 + (uint32_t)((ch ^ (row & 7)) << 4);
        size_t goff = (size_t)row * 64 + (size_t)kb * 8 + ch;
        CP_A16(dst + soff,         Ah + goff);
        CP_A16(dst + 16384 + soff, Bh + goff);
    }
}

// -------- warp-tile compute: 32x64 per warp, 64 dims/chunk, hi x hi ---------
__device__ __forceinline__ void compute_stage(uint32_t ss, int lane, int wm, int wn,
                                              float acc[2][8][4]) {
    uint32_t sAh = ss, sBh = ss + 16384;
    #pragma unroll
    for (int kk = 0; kk < 4; kk++) {
        uint32_t ah[2][4];
        #pragma unroll
        for (int i = 0; i < 2; i++) {
            int r = wm * 32 + i * 16 + (lane & 15);
            int c = (kk * 2 + (lane >> 4)) ^ (r & 7);
            ldsm4(ah[i], sAh + r * 128 + c * 16);
        }
        #pragma unroll
        for (int j16 = 0; j16 < 4; j16++) {
            int n = wn * 64 + j16 * 16 + (lane & 7) + ((lane >> 4) << 3);
            int c = (kk * 2 + ((lane >> 3) & 1)) ^ (n & 7);
            uint32_t bh[4];
            ldsm4(bh, sBh + n * 128 + c * 16);
            #pragma unroll
            for (int i = 0; i < 2; i++) {
                mma16816(acc[i][j16 * 2 + 0], ah[i], bh + 0);
                mma16816(acc[i][j16 * 2 + 1], ah[i], bh + 2);
            }
        }
    }
}

#define INS3(r, s, k) do {                                                        \
    if ((s) > v1[r]) { v3[r] = v2[r]; v2[r] = v1[r]; i2[r] = i1[r];               \
                       v1[r] = (s); i1[r] = (k); }                                \
    else if ((s) > v2[r]) { v3[r] = v2[r]; v2[r] = (s); i2[r] = (k); }            \
    else if ((s) > v3[r]) { v3[r] = (s); }                                        \
} while (0)

// -------- main dist + argmax/classify kernel --------
__global__ void __launch_bounds__(256, 2) vq_dist_kernel(float* __restrict__ out_ind_f) {
    extern __shared__ char smem[];
    uint32_t sb = smem_u32(smem);
    const int tid = threadIdx.x, lane = tid & 31, wid = tid >> 5;
    const int wm = wid & 3, wn = wid >> 2;
    const int m0 = blockIdx.x * 128;
    const uint4* Ah = (const uint4*)(g_Ah + (size_t)m0 * 256);
    const uint4* Bg = (const uint4*)g_Bh;

    // prologue: 2 chunks in flight
    load_chunk(sb + 0 * STAGE_BYTES, Ah, Bg, 0, tid);
    CP_COMMIT();
    load_chunk(sb + 1 * STAGE_BYTES, Ah, Bg, 1, tid);
    CP_COMMIT();

    float v1[4], v2[4], v3[4];
    int   i1[4], i2[4];
    #pragma unroll
    for (int r = 0; r < 4; r++) {
        v1[r] = v2[r] = v3[r] = -3.0e38f;
        i1[r] = i2[r] = 0;
    }

    for (int nt = 0; nt < 16; nt++) {
        float acc[2][8][4];
        #pragma unroll
        for (int i = 0; i < 2; i++)
            #pragma unroll
            for (int j = 0; j < 8; j++)
                #pragma unroll
                for (int q = 0; q < 4; q++) acc[i][j][q] = 0.f;

        for (int kb = 0; kb < 8; kb++) {
            int c = nt * 8 + kb;
            if (c >= 126) { CP_WAIT(0); } else { CP_WAIT(1); }
            __syncthreads();                         // single barrier per chunk
            compute_stage(sb + (c % 3) * STAGE_BYTES, lane, wm, wn, acc);
            if (c + 2 < 128) {
                load_chunk(sb + ((c + 2) % 3) * STAGE_BYTES, Ah, Bg, c + 2, tid);
                CP_COMMIT();
            }
        }

        #pragma unroll
        for (int j = 0; j < 8; j++) {
            int kb_ = nt * 128 + wn * 64 + j * 8 + (lane & 3) * 2;
            float e2a = g_e2[kb_], e2b = g_e2[kb_ + 1];
            #pragma unroll
            for (int i = 0; i < 2; i++) {
                float s0 = 2.f * acc[i][j][0] - e2a;
                float s1 = 2.f * acc[i][j][1] - e2b;
                float s2 = 2.f * acc[i][j][2] - e2a;
                float s3 = 2.f * acc[i][j][3] - e2b;
                int r0 = i * 2, r1 = i * 2 + 1;
                INS3(r0, s0, kb_);
                INS3(r0, s1, kb_ + 1);
                INS3(r1, s2, kb_);
                INS3(r1, s3, kb_ + 1);
            }
        }
    }

    // ---- per-row merge over 8 sources, classify row ----
    float* sV = (float*)smem;                   // [128][8][3]
    int*   sI = (int*)(smem + 128 * 8 * 3 * 4); // [128][8][2]
    __syncthreads();
    #pragma unroll
    for (int r = 0; r < 4; r++) {
        int row = wm * 32 + (r >> 1) * 16 + (r & 1) * 8 + (lane >> 2);
        int src = wn * 4 + (lane & 3);
        float* v = sV + (row * 8 + src) * 3;
        v[0] = v1[r]; v[1] = v2[r]; v[2] = v3[r];
        int* ii = sI + (row * 8 + src) * 2;
        ii[0] = i1[r]; ii[1] = i2[r];
    }
    __syncthreads();
    if (tid < 128) {
        float b1 = -3.0e38f; int bi1 = 0x7fffffff;
        #pragma unroll
        for (int s = 0; s < 8; s++) {
            float v = sV[(tid * 8 + s) * 3];
            int   i = sI[(tid * 8 + s) * 2];
            if (v > b1 || (v == b1 && i < bi1)) { b1 = v; bi1 = i; }
        }
        float thr = b1 - MARGIN;
        int cand[4]; int nc = 0; bool overflow = false;
        #pragma unroll
        for (int s = 0; s < 8; s++) {
            float va = sV[(tid * 8 + s) * 3 + 0];
            float vb = sV[(tid * 8 + s) * 3 + 1];
            float vc = sV[(tid * 8 + s) * 3 + 2];
            int ia = sI[(tid * 8 + s) * 2 + 0];
            int ib = sI[(tid * 8 + s) * 2 + 1];
            if (va >= thr) { if (nc < 4) cand[nc] = ia; nc++; }
            if (vb >= thr) { if (nc < 4) cand[nc] = ib; nc++; }
            if (vc >= thr) overflow = true;
        }
        int m = m0 + tid;
        g_ind[m] = bi1;
        out_ind_f[m] = (float)bi1;
        if (!overflow && nc > 1 && nc <= 4) {
            int slot = atomicAdd(&g_nlight, 1);
            g_lightm[slot] = m;
            #pragma unroll
            for (int c = 0; c < 4; c++) g_cand[(size_t)slot * 4 + c] = (c < nc) ? cand[c] : -1;
        } else if (overflow || nc > 4) {
            int slot = atomicAdd(&g_nfull, 1);
            g_fullm[slot] = m;
        }
    }
}

// -------- light fallback: exact rescore of <=4 candidates, WARP per row -----
__global__ __launch_bounds__(256) void light_kernel(const float* __restrict__ x,
                                                    const float* __restrict__ embed,
                                                    float* __restrict__ out_ind_f) {
    const int nl = g_nlight;
    const int lane = threadIdx.x & 31;
    const int wglob = blockIdx.x * 8 + (threadIdx.x >> 5);
    for (int s = wglob; s < nl; s += gridDim.x * 8) {
        int m = g_lightm[s];
        int b = m >> 13, n = m & (N_DIM - 1);
        const float* xb = x + (size_t)b * D_DIM * N_DIM + n;
        float xr[16];
        #pragma unroll
        for (int j = 0; j < 16; j++)
            xr[j] = xb[(size_t)(lane + 32 * j) * N_DIM];
        float best = -3.0e38f; int bi = 0x7fffffff;
        #pragma unroll
        for (int c = 0; c < 4; c++) {
            int k = g_cand[(size_t)s * 4 + c];
            if (k < 0) break;
            const float* e = embed + (size_t)k * D_DIM;
            float a = 0.f;
            #pragma unroll
            for (int j = 0; j < 16; j++)
                a += xr[j] * e[lane + 32 * j];
            #pragma unroll
            for (int o = 16; o > 0; o >>= 1)
                a += __shfl_xor_sync(0xffffffffu, a, o);
            float sc = 2.f * a - g_e2[k];
            if (sc > best || (sc == best && k < bi)) { best = sc; bi = k; }
        }
        if (lane == 0) { g_ind[m] = bi; out_ind_f[m] = (float)bi; }
    }
}

// -------- full fallback: exact scan of all codewords (rare) --------
__global__ __launch_bounds__(256) void full_kernel(const float* __restrict__ x,
                                                   const float* __restrict__ embed,
                                                   float* __restrict__ out_ind_f) {
    __shared__ float xr[D_DIM];
    __shared__ float bv[256];
    __shared__ int   bI[256];
    int nf = g_nfull;
    for (int f = blockIdx.x; f < nf; f += gridDim.x) {
        int m = g_fullm[f];
        int b = m >> 13, n = m & (N_DIM - 1);
        __syncthreads();
        for (int d = threadIdx.x; d < D_DIM; d += 256)
            xr[d] = x[(size_t)b * D_DIM * N_DIM + (size_t)d * N_DIM + n];
        __syncthreads();
        float best = -3.0e38f; int bi = 0x7fffffff;
        for (int c = 0; c < 8; c++) {
            int k = threadIdx.x + c * 256;
            const float4* er = (const float4*)(embed + (size_t)k * D_DIM);
            float s0 = 0.f, s1 = 0.f, s2 = 0.f, s3 = 0.f;
            #pragma unroll 8
            for (int j = 0; j < 128; j++) {
                float4 e = er[j];
                s0 += xr[4 * j + 0] * e.x;
                s1 += xr[4 * j + 1] * e.y;
                s2 += xr[4 * j + 2] * e.z;
                s3 += xr[4 * j + 3] * e.w;
            }
            float sc = 2.f * ((s0 + s1) + (s2 + s3)) - g_e2[k];
            if (sc > best || (sc == best && k < bi)) { best = sc; bi = k; }
        }
        bv[threadIdx.x] = best; bI[threadIdx.x] = bi;
        __syncthreads();
        for (int o = 128; o > 0; o >>= 1) {
            if (threadIdx.x < o) {
                float ov = bv[threadIdx.x + o]; int oi = bI[threadIdx.x + o];
                if (ov > bv[threadIdx.x] || (ov == bv[threadIdx.x] && oi < bI[threadIdx.x])) {
                    bv[threadIdx.x] = ov; bI[threadIdx.x] = oi;
                }
            }
            __syncthreads();
        }
        if (threadIdx.x == 0) { g_ind[m] = bI[0]; out_ind_f[m] = (float)bI[0]; }
        __syncthreads();
    }
}

// -------- gather v2: out[b,d,n] = embed[ind[b,n], d] --------
__global__ __launch_bounds__(512) void gather_kernel(const float* __restrict__ embed,
                                                     float* __restrict__ out) {
    __shared__ float4 tile[32 * 128];   // 64 KB
    __shared__ int inds[32];
    const int tid = threadIdx.x;
    const int bb = blockIdx.y;
    const int n0 = blockIdx.x * 32;
    if (tid < 32) inds[tid] = g_ind[bb * N_DIM + n0 + tid];
    __syncthreads();
    #pragma unroll
    for (int l = 0; l < 8; l++) {
        int i = tid + l * 512;
        int n = i >> 7, d4 = i & 127;
        float4 v = ((const float4*)(embed + (size_t)inds[n] * D_DIM))[d4];
        tile[n * 128 + (d4 ^ (n & 7))] = v;
    }
    __syncthreads();
    float* obase = out + (size_t)bb * D_DIM * N_DIM + n0;
    const float* tw = (const float*)tile;
    #pragma unroll
    for (int l = 0; l < 32; l++) {
        int i = tid + l * 512;
        int n = i & 31, d = i >> 5;
        int u = (d >> 2) ^ (n & 7);
        obase[(size_t)d * N_DIM + n] = tw[n * 512 + u * 4 + (d & 3)];
    }
}

// ---------------------------------------------------------------------------
extern "C" void kernel_launch(void* const* d_in, const int* in_sizes, int n_in,
                              void* d_out, int out_size) {
    const float* x     = (const float*)d_in[0];
    const float* embed = (const float*)d_in[1];
    float* out   = (float*)d_out;
    float* out_q = out;
    float* out_i = out + (size_t)B_DIM * D_DIM * N_DIM;
    (void)in_sizes; (void)n_in; (void)out_size;

    cudaFuncSetAttribute(vq_dist_kernel, cudaFuncAttributeMaxDynamicSharedMemorySize, SM_DIST);

    prep_embed_kernel<<<K_CB, 128>>>(embed);
    prep_x_kernel<<<dim3(N_DIM / 64, B_DIM), 256>>>(x);
    vq_dist_kernel<<<M_ROWS / 128, 256, SM_DIST>>>(out_i);
    light_kernel<<<1024, 256>>>(x, embed, out_i);
    full_kernel<<<64, 256>>>(x, embed, out_i);
    gather_kernel<<<dim3(N_DIM / 32, B_DIM), 512>>>(embed, out_q);
}